// round 1
// baseline (speedup 1.0000x reference)
#include <cuda_runtime.h>

// ---------------- problem constants ----------------
#define Tdim 8
#define Hdim 24
#define Wdim 24
#define NSP  4608        // 8*24*24
#define TP   10
#define HP   26
#define WP   26
#define NPADS 6760       // 10*26*26
#define C    256
#define KTAPS 27
#define KTOT 6912        // 27*256

// ---------------- static device scratch ----------------
__device__ float g_xpad[NPADS * C];      // x, channels-last, zero-padded spatial
__device__ float g_fA[NPADS * C];        // feature ping
__device__ float g_fB[NPADS * C];        // feature pong
__device__ float g_offs[NSP * 81];       // offsets, [n][co]
__device__ float g_col[NSP * KTOT];      // deform im2col: [n][tap][ci]
__device__ float g_w1[KTOT * C];         // transformed weights [tap][ci][co]
__device__ float g_w2[KTOT * C];
__device__ float g_w3[KTOT * C];
__device__ float g_wd[KTOT * 128];       // def weights padded 81 -> 128
__device__ float g_wc[KTOT * C];

// ---------------- helpers ----------------
__device__ __forceinline__ int pidx(int n) {
    int t = n / 576;
    int r = n - t * 576;
    int h = r / 24;
    int w = r - h * 24;
    return ((t + 1) * HP + (h + 1)) * WP + (w + 1);
}

__device__ __forceinline__ int tap_shift(int tap) {
    int kt = tap / 9;
    int kh = (tap / 3) % 3;
    int kw = tap % 3;
    return ((kt - 1) * HP + (kh - 1)) * WP + (kw - 1);
}

// ---------------- utility kernels ----------------
__global__ void zero_kernel(float* __restrict__ p, int n) {
    int i = blockIdx.x * blockDim.x + threadIdx.x;
    int stride = gridDim.x * blockDim.x;
    for (; i < n; i += stride) p[i] = 0.0f;
}

// x [ci][n] -> xpad [p(n)][ci]
__global__ void transpose_x_kernel(const float* __restrict__ x, float* __restrict__ xpad) {
    int n = blockIdx.x;
    int ci = threadIdx.x;
    int p = pidx(n);
    xpad[p * C + ci] = x[ci * NSP + n];
}

// w [co][ci][tap] -> w2 [tap*256+ci][co] (row = blockIdx.x), zero pad co >= coutReal
__global__ void wtrans_kernel(const float* __restrict__ src, float* __restrict__ dst,
                              int coutReal, int ldo) {
    int row = blockIdx.x;            // tap*256 + ci
    int tap = row >> 8;
    int ci  = row & 255;
    int co  = threadIdx.x;
    float v = 0.0f;
    if (co < coutReal) v = src[(co * C + ci) * KTAPS + tap];
    dst[row * ldo + co] = v;
}

// ---------------- deformable im2col ----------------
// grid (NSP, 27), 64 threads; each thread: 4 channels (float4)
__global__ void col_build_kernel() {
    int n = blockIdx.x;
    int k = blockIdx.y;
    int tid = threadIdx.x;

    int t = n / 576;
    int r = n - t * 576;
    int h = r / 24;
    int w = r - h * 24;

    float offT = g_offs[n * 81 + k * 3 + 0];
    float offH = g_offs[n * 81 + k * 3 + 1];
    float offW = g_offs[n * 81 + k * 3 + 2];

    float pt = (float)t + (float)(k / 9 - 1) + offT;
    float ph = (float)h + (float)((k / 3) % 3 - 1) + offH;
    float pw = (float)w + (float)(k % 3 - 1) + offW;

    float ft = floorf(pt), fh = floorf(ph), fw = floorf(pw);
    float at = pt - ft, ah = ph - fh, aw = pw - fw;
    int it = (int)ft, ih = (int)fh, iw = (int)fw;

    float ax = 0.f, ay = 0.f, az = 0.f, awv = 0.f;
    #pragma unroll
    for (int dt = 0; dt < 2; dt++) {
        int tt = it + dt;
        float wt = dt ? at : (1.0f - at);
        bool vt = (tt >= 0) && (tt < Tdim);
        int tc = min(max(tt, 0), Tdim - 1);
        #pragma unroll
        for (int dh = 0; dh < 2; dh++) {
            int hh = ih + dh;
            float wh = dh ? ah : (1.0f - ah);
            bool vh = (hh >= 0) && (hh < Hdim);
            int hc = min(max(hh, 0), Hdim - 1);
            #pragma unroll
            for (int dw = 0; dw < 2; dw++) {
                int ww_ = iw + dw;
                float wwf = dw ? aw : (1.0f - aw);
                bool vw = (ww_ >= 0) && (ww_ < Wdim);
                int wc = min(max(ww_, 0), Wdim - 1);
                float wgt = wt * wh * wwf;
                if (!(vt && vh && vw)) wgt = 0.0f;
                int pp = ((tc + 1) * HP + (hc + 1)) * WP + (wc + 1);
                const float4 v = *(const float4*)&g_xpad[pp * C + tid * 4];
                ax += wgt * v.x; ay += wgt * v.y; az += wgt * v.z; awv += wgt * v.w;
            }
        }
    }
    float4 o; o.x = ax; o.y = ay; o.z = az; o.w = awv;
    *(float4*)&g_col[(n * KTAPS + k) * C + tid * 4] = o;
}

// ---------------- GEMM ----------------
// C[M=4608 spatial, N=Cout] = A[M, K=6912] * B[K, N] + bias, with epilogue variants
// amode 0: A = padded feature map (tap-shifted addressing)
// amode 1: A = g_col (dense rows, stride KTOT)
// epi 0: relu(acc+bias) -> padded channels-last dst
// epi 1: acc+bias -> dst[n*coutReal + co] (guarded, offsets conv)
// epi 2: acc+bias -> dst[co*NSP + n]      (final NCDHW output)
#define BM 64
#define BN 128
#define BK 16

__global__ __launch_bounds__(128) void gemm_kernel(
    const float* __restrict__ A, const float* __restrict__ Bw,
    const float* __restrict__ bias, float* __restrict__ Dst,
    int ldb, int coutReal, int amode, int epi)
{
    __shared__ float As[BK][BM];
    __shared__ float Bs[BK][BN];

    int tid = threadIdx.x;
    int bm0 = blockIdx.x * BM;
    int bn0 = blockIdx.y * BN;

    // A loader: 2 rows per thread, float4 within-chunk
    int lane4 = tid & 3;
    int arow  = tid >> 2;           // 0..31
    int gmA0 = bm0 + arow;
    int gmA1 = gmA0 + 32;
    int base0, base1;
    if (amode == 0) { base0 = pidx(gmA0) * C; base1 = pidx(gmA1) * C; }
    else            { base0 = gmA0 * KTOT;    base1 = gmA1 * KTOT; }

    // B loader
    int bkrow = tid >> 5;           // 0..3
    int bkcol = (tid & 31) * 4;

    // compute mapping
    int tm = tid & 7;               // 8 m-groups
    int tn = tid >> 3;              // 16 n-groups

    float acc[8][8];
    #pragma unroll
    for (int i = 0; i < 8; i++)
        #pragma unroll
        for (int j = 0; j < 8; j++) acc[i][j] = 0.0f;

    const int NCHUNK = KTOT / BK;   // 432
    for (int kc = 0; kc < NCHUNK; kc++) {
        int kg0 = kc * BK;
        float4 a0, a1;
        if (amode == 0) {
            int tap = kg0 >> 8;
            int shift = tap_shift(tap) * C;
            int off = (kg0 & 255) + lane4 * 4;
            a0 = *(const float4*)(A + base0 + shift + off);
            a1 = *(const float4*)(A + base1 + shift + off);
        } else {
            int off = kg0 + lane4 * 4;
            a0 = *(const float4*)(A + base0 + off);
            a1 = *(const float4*)(A + base1 + off);
        }
        float4 b0 = *(const float4*)(Bw + (kg0 + bkrow     ) * ldb + bn0 + bkcol);
        float4 b1 = *(const float4*)(Bw + (kg0 + bkrow +  4) * ldb + bn0 + bkcol);
        float4 b2 = *(const float4*)(Bw + (kg0 + bkrow +  8) * ldb + bn0 + bkcol);
        float4 b3 = *(const float4*)(Bw + (kg0 + bkrow + 12) * ldb + bn0 + bkcol);

        __syncthreads();
        int k0 = lane4 * 4;
        As[k0 + 0][arow] = a0.x; As[k0 + 1][arow] = a0.y;
        As[k0 + 2][arow] = a0.z; As[k0 + 3][arow] = a0.w;
        As[k0 + 0][arow + 32] = a1.x; As[k0 + 1][arow + 32] = a1.y;
        As[k0 + 2][arow + 32] = a1.z; As[k0 + 3][arow + 32] = a1.w;
        *(float4*)&Bs[bkrow     ][bkcol] = b0;
        *(float4*)&Bs[bkrow +  4][bkcol] = b1;
        *(float4*)&Bs[bkrow +  8][bkcol] = b2;
        *(float4*)&Bs[bkrow + 12][bkcol] = b3;
        __syncthreads();

        #pragma unroll
        for (int k = 0; k < BK; k++) {
            float av[8], bv[8];
            *(float4*)&av[0] = *(const float4*)&As[k][tm * 8];
            *(float4*)&av[4] = *(const float4*)&As[k][tm * 8 + 4];
            *(float4*)&bv[0] = *(const float4*)&Bs[k][tn * 8];
            *(float4*)&bv[4] = *(const float4*)&Bs[k][tn * 8 + 4];
            #pragma unroll
            for (int i = 0; i < 8; i++)
                #pragma unroll
                for (int j = 0; j < 8; j++)
                    acc[i][j] += av[i] * bv[j];
        }
    }

    int gn0 = bn0 + tn * 8;
    int gm0 = bm0 + tm * 8;

    if (epi == 0) {
        float bv[8];
        #pragma unroll
        for (int j = 0; j < 8; j++) bv[j] = bias[gn0 + j];
        #pragma unroll
        for (int i = 0; i < 8; i++) {
            int pb = pidx(gm0 + i) * C;
            #pragma unroll
            for (int j0 = 0; j0 < 8; j0 += 4) {
                float4 v;
                v.x = fmaxf(acc[i][j0 + 0] + bv[j0 + 0], 0.0f);
                v.y = fmaxf(acc[i][j0 + 1] + bv[j0 + 1], 0.0f);
                v.z = fmaxf(acc[i][j0 + 2] + bv[j0 + 2], 0.0f);
                v.w = fmaxf(acc[i][j0 + 3] + bv[j0 + 3], 0.0f);
                *(float4*)&Dst[pb + gn0 + j0] = v;
            }
        }
    } else if (epi == 1) {
        #pragma unroll
        for (int i = 0; i < 8; i++) {
            int gm = gm0 + i;
            #pragma unroll
            for (int j = 0; j < 8; j++) {
                int gn = gn0 + j;
                if (gn < coutReal)
                    Dst[gm * coutReal + gn] = acc[i][j] + bias[gn];
            }
        }
    } else {
        // transposed store: dst[co][n]; i is contiguous in n -> float4 over i
        #pragma unroll
        for (int j = 0; j < 8; j++) {
            int gn = gn0 + j;
            float b = bias[gn];
            float4 v0, v1;
            v0.x = acc[0][j] + b; v0.y = acc[1][j] + b;
            v0.z = acc[2][j] + b; v0.w = acc[3][j] + b;
            v1.x = acc[4][j] + b; v1.y = acc[5][j] + b;
            v1.z = acc[6][j] + b; v1.w = acc[7][j] + b;
            *(float4*)&Dst[gn * NSP + gm0]     = v0;
            *(float4*)&Dst[gn * NSP + gm0 + 4] = v1;
        }
    }
}

// ---------------- launch ----------------
extern "C" void kernel_launch(void* const* d_in, const int* in_sizes, int n_in,
                              void* d_out, int out_size)
{
    const float* x   = (const float*)d_in[0];
    const float* l1w = (const float*)d_in[1];
    const float* l1b = (const float*)d_in[2];
    const float* l2w = (const float*)d_in[3];
    const float* l2b = (const float*)d_in[4];
    const float* l3w = (const float*)d_in[5];
    const float* l3b = (const float*)d_in[6];
    const float* dw  = (const float*)d_in[7];
    const float* db  = (const float*)d_in[8];
    const float* cw  = (const float*)d_in[9];
    const float* cb  = (const float*)d_in[10];
    float* out = (float*)d_out;

    float *xpad, *fA, *fB, *offs, *col, *w1, *w2, *w3, *wd, *wc;
    cudaGetSymbolAddress((void**)&xpad, g_xpad);
    cudaGetSymbolAddress((void**)&fA,   g_fA);
    cudaGetSymbolAddress((void**)&fB,   g_fB);
    cudaGetSymbolAddress((void**)&offs, g_offs);
    cudaGetSymbolAddress((void**)&col,  g_col);
    cudaGetSymbolAddress((void**)&w1,   g_w1);
    cudaGetSymbolAddress((void**)&w2,   g_w2);
    cudaGetSymbolAddress((void**)&w3,   g_w3);
    cudaGetSymbolAddress((void**)&wd,   g_wd);
    cudaGetSymbolAddress((void**)&wc,   g_wc);

    // zero padded buffers (borders must be 0 every run; interior overwritten)
    zero_kernel<<<1024, 256>>>(xpad, NPADS * C);
    zero_kernel<<<1024, 256>>>(fA,   NPADS * C);
    zero_kernel<<<1024, 256>>>(fB,   NPADS * C);

    // layout transforms
    transpose_x_kernel<<<NSP, 256>>>(x, xpad);
    wtrans_kernel<<<KTOT, 256>>>(l1w, w1, 256, 256);
    wtrans_kernel<<<KTOT, 256>>>(l2w, w2, 256, 256);
    wtrans_kernel<<<KTOT, 256>>>(l3w, w3, 256, 256);
    wtrans_kernel<<<KTOT, 128>>>(dw,  wd,  81, 128);
    wtrans_kernel<<<KTOT, 256>>>(cw,  wc, 256, 256);

    dim3 g2(NSP / BM, 2), g1(NSP / BM, 1);
    // conv1: x -> fA (relu)
    gemm_kernel<<<g2, 128>>>(xpad, w1, l1b, fA, 256, 256, 0, 0);
    // conv2: fA -> fB (relu)
    gemm_kernel<<<g2, 128>>>(fA, w2, l2b, fB, 256, 256, 0, 0);
    // conv3: fB -> fA (relu)
    gemm_kernel<<<g2, 128>>>(fB, w3, l3b, fA, 256, 256, 0, 0);
    // offsets conv: fA -> offs (81 channels, no relu)
    gemm_kernel<<<g1, 128>>>(fA, wd, db, offs, 128, 81, 0, 1);
    // deformable im2col (reads g_offs, g_xpad; writes g_col)
    col_build_kernel<<<dim3(NSP, KTAPS), 64>>>();
    // deformable conv: col -> out (transposed NCDHW store)
    gemm_kernel<<<g2, 128>>>(col, wc, cb, out, 256, 256, 1, 2);
}

// round 2
// speedup vs baseline: 1.2902x; 1.2902x over previous
#include <cuda_runtime.h>

// ---------------- problem constants ----------------
#define Tdim 8
#define Hdim 24
#define Wdim 24
#define NSP  4608        // 8*24*24
#define TP   10
#define HP   26
#define WP   26
#define NPADS 6760       // 10*26*26
#define C    256
#define KTAPS 27
#define KTOT 6912        // 27*256
#define BK   16
#define BN   128

// ---------------- static device scratch ----------------
__device__ float g_xpad[NPADS * C];      // x, channels-last, zero-padded spatial
__device__ float g_fA[NPADS * C];        // feature ping
__device__ float g_fB[NPADS * C];        // feature pong
__device__ float g_offs[NSP * 81];       // offsets, [n][co]
__device__ float g_col[NSP * KTOT];      // deform im2col: [n][tap][ci]
__device__ float g_w1[KTOT * C];         // transformed weights [tap][ci][co]
__device__ float g_w2[KTOT * C];
__device__ float g_w3[KTOT * C];
__device__ float g_wd[KTOT * 128];       // def weights padded 81 -> 128
__device__ float g_wc[KTOT * C];

// ---------------- helpers ----------------
__device__ __forceinline__ int pidx(int n) {
    int t = n / 576;
    int r = n - t * 576;
    int h = r / 24;
    int w = r - h * 24;
    return ((t + 1) * HP + (h + 1)) * WP + (w + 1);
}

__device__ __forceinline__ int tap_shift(int tap) {
    int kt = tap / 9;
    int kh = (tap / 3) % 3;
    int kw = tap % 3;
    return ((kt - 1) * HP + (kh - 1)) * WP + (kw - 1);
}

// packed fp32x2 FMA: d = a*b + d (elementwise on pairs). Exact same rounding
// as two scalar fma.rn.f32 -> bitwise identical numerics, 2x fma-pipe rate.
__device__ __forceinline__ void fma2(unsigned long long& d,
                                     unsigned long long a,
                                     unsigned long long b) {
    asm("fma.rn.f32x2 %0, %1, %2, %0;" : "+l"(d) : "l"(a), "l"(b));
}
__device__ __forceinline__ unsigned long long dup2(float a) {
    unsigned long long d;
    asm("mov.b64 %0, {%1, %1};" : "=l"(d) : "f"(a));
    return d;
}
__device__ __forceinline__ void unpack2(unsigned long long v, float& lo, float& hi) {
    asm("mov.b64 {%0, %1}, %2;" : "=f"(lo), "=f"(hi) : "l"(v));
}

// ---------------- utility kernels ----------------
__global__ void zero_kernel(float* __restrict__ p, int n) {
    int i = blockIdx.x * blockDim.x + threadIdx.x;
    int stride = gridDim.x * blockDim.x;
    for (; i < n; i += stride) p[i] = 0.0f;
}

// x [ci][n] -> xpad [p(n)][ci]
__global__ void transpose_x_kernel(const float* __restrict__ x, float* __restrict__ xpad) {
    int n = blockIdx.x;
    int ci = threadIdx.x;
    int p = pidx(n);
    xpad[p * C + ci] = x[ci * NSP + n];
}

// w [co][ci][tap] -> dst [tap*256+ci][co], coalesced via smem transpose.
// grid = 256 (ci), 256 threads.
__global__ void wtrans2_kernel(const float* __restrict__ src, float* __restrict__ dst,
                               int coutReal, int ldo) {
    __shared__ float s[KTAPS * 256];
    int ci = blockIdx.x;
    int tid = threadIdx.x;
    for (int idx = tid; idx < coutReal * KTAPS; idx += 256) {
        int co = idx / KTAPS;
        int tap = idx - co * KTAPS;
        s[tap * 256 + co] = src[(co * C + ci) * KTAPS + tap];
    }
    __syncthreads();
    for (int idx = tid; idx < KTAPS * ldo; idx += 256) {
        int tap = idx / ldo;
        int co = idx - tap * ldo;
        float v = (co < coutReal) ? s[tap * 256 + co] : 0.0f;
        dst[(tap * 256 + ci) * ldo + co] = v;
    }
}

// ---------------- deformable im2col ----------------
// grid (NSP, 27), 64 threads; each thread: 4 channels (float4)
__global__ void col_build_kernel() {
    int n = blockIdx.x;
    int k = blockIdx.y;
    int tid = threadIdx.x;

    int t = n / 576;
    int r = n - t * 576;
    int h = r / 24;
    int w = r - h * 24;

    float offT = g_offs[n * 81 + k * 3 + 0];
    float offH = g_offs[n * 81 + k * 3 + 1];
    float offW = g_offs[n * 81 + k * 3 + 2];

    float pt = (float)t + (float)(k / 9 - 1) + offT;
    float ph = (float)h + (float)((k / 3) % 3 - 1) + offH;
    float pw = (float)w + (float)(k % 3 - 1) + offW;

    float ft = floorf(pt), fh = floorf(ph), fw = floorf(pw);
    float at = pt - ft, ah = ph - fh, aw = pw - fw;
    int it = (int)ft, ih = (int)fh, iw = (int)fw;

    float ax = 0.f, ay = 0.f, az = 0.f, awv = 0.f;
    #pragma unroll
    for (int dt = 0; dt < 2; dt++) {
        int tt = it + dt;
        float wt = dt ? at : (1.0f - at);
        bool vt = (tt >= 0) && (tt < Tdim);
        int tc = min(max(tt, 0), Tdim - 1);
        #pragma unroll
        for (int dh = 0; dh < 2; dh++) {
            int hh = ih + dh;
            float wh = dh ? ah : (1.0f - ah);
            bool vh = (hh >= 0) && (hh < Hdim);
            int hc = min(max(hh, 0), Hdim - 1);
            #pragma unroll
            for (int dw = 0; dw < 2; dw++) {
                int ww_ = iw + dw;
                float wwf = dw ? aw : (1.0f - aw);
                bool vw = (ww_ >= 0) && (ww_ < Wdim);
                int wc = min(max(ww_, 0), Wdim - 1);
                float wgt = wt * wh * wwf;
                if (!(vt && vh && vw)) wgt = 0.0f;
                int pp = ((tc + 1) * HP + (hc + 1)) * WP + (wc + 1);
                const float4 v = *(const float4*)&g_xpad[pp * C + tid * 4];
                ax += wgt * v.x; ay += wgt * v.y; az += wgt * v.z; awv += wgt * v.w;
            }
        }
    }
    float4 o; o.x = ax; o.y = ay; o.z = az; o.w = awv;
    *(float4*)&g_col[(n * KTAPS + k) * C + tid * 4] = o;
}

// ---------------- GEMM (f32x2, double-buffered, 256 threads) ----------------
// C[M=4608, N] = A[M, K=6912] * B[K, N] + bias
// TM: per-thread M rows (4 -> BM=64, 2 -> BM=32). Per-thread N = 8 (4 pairs).
// AMODE 0: A = padded feature map (tap-shifted addressing)
// AMODE 1: A = g_col (dense rows, stride KTOT)
// EPI 0: relu(acc+bias) -> padded channels-last dst
// EPI 1: acc+bias -> dst[n*coutReal + co] (guarded, offsets conv)
// EPI 2: acc+bias -> dst[co*NSP + n]      (final NCDHW output)
template<int TM, int AMODE, int EPI>
__global__ __launch_bounds__(256) void gemm2_kernel(
    const float* __restrict__ A, const float* __restrict__ Bw,
    const float* __restrict__ bias, float* __restrict__ Dst,
    int ldb, int coutReal)
{
    constexpr int BM = TM * 16;
    __shared__ float As[2][BK][BM];
    __shared__ float Bs[2][BK][BN];

    int tid = threadIdx.x;
    int bm0 = blockIdx.x * BM;
    int bn0 = blockIdx.y * BN;

    // ---- A loader mapping: one float4 per (active) thread per chunk
    int lane4 = tid & 3;
    int arow  = tid >> 2;                  // 0..63
    bool aact = (TM == 4) || (tid < 128);  // TM=2 uses 128 loader threads
    int abase = 0;
    if (aact) {
        int gm = bm0 + arow;
        abase = (AMODE == 0) ? pidx(gm) * C : gm * KTOT;
    }

    // ---- B loader mapping: two float4 per thread per chunk
    int bkrow = tid >> 5;                  // 0..7
    int bkcol = (tid & 31) * 4;
    const float* bptr = Bw + bn0 + bkcol;

    // ---- compute mapping
    int tm_ = tid & 15;                    // m-group
    int tn  = tid >> 4;                    // n-group (8 cols = 4 pairs)

    unsigned long long acc[TM][4];
    #pragma unroll
    for (int i = 0; i < TM; i++)
        #pragma unroll
        for (int p = 0; p < 4; p++) acc[i][p] = 0ull;

    float4 aN = make_float4(0.f, 0.f, 0.f, 0.f);
    float4 bN0, bN1;

    auto gloadA = [&](int kg0) -> float4 {
        int off;
        if (AMODE == 0) {
            int tap = kg0 >> 8;
            off = tap_shift(tap) * C + (kg0 & 255) + lane4 * 4;
        } else {
            off = kg0 + lane4 * 4;
        }
        return *(const float4*)(A + abase + off);
    };

    // prologue: chunk 0
    if (aact) aN = gloadA(0);
    bN0 = *(const float4*)(bptr + (0 + bkrow) * ldb);
    bN1 = *(const float4*)(bptr + (8 + bkrow) * ldb);
    {
        int k0 = lane4 * 4;
        if (aact) {
            As[0][k0 + 0][arow] = aN.x; As[0][k0 + 1][arow] = aN.y;
            As[0][k0 + 2][arow] = aN.z; As[0][k0 + 3][arow] = aN.w;
        }
        *(float4*)&Bs[0][bkrow][bkcol]     = bN0;
        *(float4*)&Bs[0][bkrow + 8][bkcol] = bN1;
    }
    __syncthreads();

    const int NCHUNK = KTOT / BK;          // 432
    for (int kc = 0; kc < NCHUNK; kc++) {
        int cur = kc & 1;
        int nxt = kc + 1;
        bool have_next = (nxt < NCHUNK);
        if (have_next) {
            int kg0 = nxt * BK;
            if (aact) aN = gloadA(kg0);
            bN0 = *(const float4*)(bptr + (kg0 + bkrow) * ldb);
            bN1 = *(const float4*)(bptr + (kg0 + 8 + bkrow) * ldb);
        }

        #pragma unroll
        for (int k = 0; k < BK; k++) {
            float a[TM];
            if (TM == 4) *(float4*)a = *(const float4*)&As[cur][k][tm_ * 4];
            else         *(float2*)a = *(const float2*)&As[cur][k][tm_ * 2];
            ulonglong2 bq0 = *(const ulonglong2*)&Bs[cur][k][tn * 8];
            ulonglong2 bq1 = *(const ulonglong2*)&Bs[cur][k][tn * 8 + 4];
            unsigned long long bp0 = bq0.x, bp1 = bq0.y, bp2 = bq1.x, bp3 = bq1.y;
            #pragma unroll
            for (int i = 0; i < TM; i++) {
                unsigned long long ad = dup2(a[i]);
                fma2(acc[i][0], ad, bp0);
                fma2(acc[i][1], ad, bp1);
                fma2(acc[i][2], ad, bp2);
                fma2(acc[i][3], ad, bp3);
            }
        }

        if (have_next) {
            int k0 = lane4 * 4;
            int nb = nxt & 1;
            if (aact) {
                As[nb][k0 + 0][arow] = aN.x; As[nb][k0 + 1][arow] = aN.y;
                As[nb][k0 + 2][arow] = aN.z; As[nb][k0 + 3][arow] = aN.w;
            }
            *(float4*)&Bs[nb][bkrow][bkcol]     = bN0;
            *(float4*)&Bs[nb][bkrow + 8][bkcol] = bN1;
        }
        __syncthreads();
    }

    // ---- epilogue
    int gm0 = bm0 + tm_ * TM;
    int gn0 = bn0 + tn * 8;

    float f[TM][8];
    #pragma unroll
    for (int i = 0; i < TM; i++)
        #pragma unroll
        for (int p = 0; p < 4; p++)
            unpack2(acc[i][p], f[i][2 * p], f[i][2 * p + 1]);

    if (EPI == 0) {
        float bj[8];
        #pragma unroll
        for (int j = 0; j < 8; j++) bj[j] = bias[gn0 + j];
        #pragma unroll
        for (int i = 0; i < TM; i++) {
            int pb = pidx(gm0 + i) * C;
            float4 v0, v1;
            v0.x = fmaxf(f[i][0] + bj[0], 0.f); v0.y = fmaxf(f[i][1] + bj[1], 0.f);
            v0.z = fmaxf(f[i][2] + bj[2], 0.f); v0.w = fmaxf(f[i][3] + bj[3], 0.f);
            v1.x = fmaxf(f[i][4] + bj[4], 0.f); v1.y = fmaxf(f[i][5] + bj[5], 0.f);
            v1.z = fmaxf(f[i][6] + bj[6], 0.f); v1.w = fmaxf(f[i][7] + bj[7], 0.f);
            *(float4*)&Dst[pb + gn0]     = v0;
            *(float4*)&Dst[pb + gn0 + 4] = v1;
        }
    } else if (EPI == 1) {
        #pragma unroll
        for (int i = 0; i < TM; i++) {
            int gm = gm0 + i;
            #pragma unroll
            for (int j = 0; j < 8; j++) {
                int gn = gn0 + j;
                if (gn < coutReal)
                    Dst[gm * coutReal + gn] = f[i][j] + bias[gn];
            }
        }
    } else {
        // transposed store: dst[co][n]; TM==4 rows contiguous in n
        #pragma unroll
        for (int j = 0; j < 8; j++) {
            int gn = gn0 + j;
            float b = bias[gn];
            float4 v;
            v.x = f[0][j] + b; v.y = f[1][j] + b;
            v.z = f[2][j] + b; v.w = f[3][j] + b;
            *(float4*)&Dst[gn * NSP + gm0] = v;
        }
    }
}

// ---------------- launch ----------------
extern "C" void kernel_launch(void* const* d_in, const int* in_sizes, int n_in,
                              void* d_out, int out_size)
{
    const float* x   = (const float*)d_in[0];
    const float* l1w = (const float*)d_in[1];
    const float* l1b = (const float*)d_in[2];
    const float* l2w = (const float*)d_in[3];
    const float* l2b = (const float*)d_in[4];
    const float* l3w = (const float*)d_in[5];
    const float* l3b = (const float*)d_in[6];
    const float* dw  = (const float*)d_in[7];
    const float* db  = (const float*)d_in[8];
    const float* cw  = (const float*)d_in[9];
    const float* cb  = (const float*)d_in[10];
    float* out = (float*)d_out;

    float *xpad, *fA, *fB, *offs, *col, *w1, *w2, *w3, *wd, *wc;
    cudaGetSymbolAddress((void**)&xpad, g_xpad);
    cudaGetSymbolAddress((void**)&fA,   g_fA);
    cudaGetSymbolAddress((void**)&fB,   g_fB);
    cudaGetSymbolAddress((void**)&offs, g_offs);
    cudaGetSymbolAddress((void**)&col,  g_col);
    cudaGetSymbolAddress((void**)&w1,   g_w1);
    cudaGetSymbolAddress((void**)&w2,   g_w2);
    cudaGetSymbolAddress((void**)&w3,   g_w3);
    cudaGetSymbolAddress((void**)&wd,   g_wd);
    cudaGetSymbolAddress((void**)&wc,   g_wc);

    // zero padded buffers (borders must be 0 every run; interior overwritten)
    zero_kernel<<<1024, 256>>>(xpad, NPADS * C);
    zero_kernel<<<1024, 256>>>(fA,   NPADS * C);
    zero_kernel<<<1024, 256>>>(fB,   NPADS * C);

    // layout transforms
    transpose_x_kernel<<<NSP, 256>>>(x, xpad);
    wtrans2_kernel<<<C, 256>>>(l1w, w1, 256, 256);
    wtrans2_kernel<<<C, 256>>>(l2w, w2, 256, 256);
    wtrans2_kernel<<<C, 256>>>(l3w, w3, 256, 256);
    wtrans2_kernel<<<C, 256>>>(dw,  wd,  81, 128);
    wtrans2_kernel<<<C, 256>>>(cw,  wc, 256, 256);

    dim3 gBig(NSP / 64, 2);    // 72 x 2 = 144 blocks
    dim3 gOff(NSP / 32, 1);    // 144 blocks
    // conv1: x -> fA (relu)
    gemm2_kernel<4, 0, 0><<<gBig, 256>>>(xpad, w1, l1b, fA, 256, 256);
    // conv2: fA -> fB (relu)
    gemm2_kernel<4, 0, 0><<<gBig, 256>>>(fA, w2, l2b, fB, 256, 256);
    // conv3: fB -> fA (relu)
    gemm2_kernel<4, 0, 0><<<gBig, 256>>>(fB, w3, l3b, fA, 256, 256);
    // offsets conv: fA -> offs (81 channels, no relu)
    gemm2_kernel<2, 0, 1><<<gOff, 256>>>(fA, wd, db, offs, 128, 81);
    // deformable im2col (reads g_offs, g_xpad; writes g_col)
    col_build_kernel<<<dim3(NSP, KTAPS), 64>>>();
    // deformable conv: col -> out (transposed NCDHW store)
    gemm2_kernel<4, 1, 2><<<gBig, 256>>>(col, wc, cb, out, 256, 256);
}

// round 5
// speedup vs baseline: 2.0426x; 1.5832x over previous
#include <cuda_runtime.h>
#include <cuda_bf16.h>
#include <cstdint>

typedef unsigned int u32;
typedef unsigned long long u64;

// ---------------- problem constants ----------------
#define Tdim 8
#define Hdim 24
#define Wdim 24
#define NSP  4608        // 8*24*24
#define HP   26
#define WP   26
#define NPADS 6760       // 10*26*26
#define C    256
#define KTAPS 27
#define KTOT 6912        // 27*256
#define KC   32          // k per chunk
#define NCH  216         // KTOT/KC
#define BM   128
#define BN   128
#define STAGE_BYTES 32768      // Ah|Al|Bh|Bl tiles, 8KB each
#define DSMEM_BYTES (2*STAGE_BYTES)

// ---------------- static device scratch ----------------
__device__ float g_xpad[NPADS * C];
__device__ __nv_bfloat16 g_xph[NPADS * C], g_xpl[NPADS * C];
__device__ __nv_bfloat16 g_fhA[NPADS * C], g_flA[NPADS * C];
__device__ __nv_bfloat16 g_fhB[NPADS * C], g_flB[NPADS * C];
__device__ float g_offs[NSP * 81];
__device__ __nv_bfloat16 g_colh[(size_t)NSP * KTOT], g_coll[(size_t)NSP * KTOT];
__device__ __nv_bfloat16 g_w1h[C * KTOT], g_w1l[C * KTOT];
__device__ __nv_bfloat16 g_w2h[C * KTOT], g_w2l[C * KTOT];
__device__ __nv_bfloat16 g_w3h[C * KTOT], g_w3l[C * KTOT];
__device__ __nv_bfloat16 g_wch[C * KTOT], g_wcl[C * KTOT];
__device__ __nv_bfloat16 g_wdh[128 * KTOT], g_wdl[128 * KTOT];

// tap spatial shift in padded space: ((kt-1)*HP + (kh-1))*WP + (kw-1)
__constant__ int c_shift[27] = {
  -703, -702, -701, -677, -676, -675, -651, -650, -649,
   -27,  -26,  -25,   -1,    0,    1,   25,   26,   27,
   649,  650,  651,  675,  676,  677,  701,  702,  703 };

// ---------------- helpers ----------------
__device__ __forceinline__ int pidx(int n) {
    int t = n / 576;
    int r = n - t * 576;
    int h = r / 24;
    int w = r - h * 24;
    return ((t + 1) * HP + (h + 1)) * WP + (w + 1);
}

__device__ __forceinline__ u32 smem_u32(const void* p) {
    u32 a;
    asm("{ .reg .u64 t; cvta.to.shared.u64 t, %1; cvt.u32.u64 %0, t; }" : "=r"(a) : "l"(p));
    return a;
}

// smem layout for a 128row x 32k bf16 tile (8KB): two consecutive rows share a
// 128B pair (8 x 16B chunks). Chunk index within pair c = (row&1)*4 + kg is
// XOR-permuted by the pair index: pos = c ^ ((row>>1)&7). Bijective, and the
// 8 row-addresses of every ldmatrix 8x8 matrix land in 8 distinct 16B slots.
__device__ __forceinline__ u32 swofs(u32 row, u32 kg) {
    return ((row >> 1) << 7) + (((((row & 1) << 2) + kg) ^ ((row >> 1) & 7)) << 4);
}

#define CPASYNC(dst, src) \
    asm volatile("cp.async.cg.shared.global [%0], [%1], 16;" :: "r"(dst), "l"(src))
#define CPCOMMIT() asm volatile("cp.async.commit_group;" ::: "memory")
#define CPWAIT(n)  asm volatile("cp.async.wait_group %0;" :: "n"(n) : "memory")

#define LDM4(r, a) \
    asm volatile("ldmatrix.sync.aligned.m8n8.x4.shared.b16 {%0,%1,%2,%3}, [%4];" \
        : "=r"((r)[0]), "=r"((r)[1]), "=r"((r)[2]), "=r"((r)[3]) : "r"(a))

#define MMA(d, a, b0, b1) \
    asm volatile("mma.sync.aligned.m16n8k16.row.col.f32.bf16.bf16.f32 " \
        "{%0,%1,%2,%3}, {%4,%5,%6,%7}, {%8,%9}, {%0,%1,%2,%3};" \
        : "+f"((d)[0]), "+f"((d)[1]), "+f"((d)[2]), "+f"((d)[3]) \
        : "r"((a)[0]), "r"((a)[1]), "r"((a)[2]), "r"((a)[3]), "r"(b0), "r"(b1))

// ---------------- utility kernels ----------------
__global__ void zero8(u64* __restrict__ p, int n) {
    int i = blockIdx.x * blockDim.x + threadIdx.x;
    int s = gridDim.x * blockDim.x;
    for (; i < n; i += s) p[i] = 0ull;
}

// x [ci][n] -> xpad(+bf16 hi/lo) [p(n)][ci]
__global__ void transpose_x_kernel(const float* __restrict__ x) {
    int n = blockIdx.x;
    int ci = threadIdx.x;
    int p = pidx(n);
    float v = x[ci * NSP + n];
    g_xpad[p * C + ci] = v;
    __nv_bfloat16 h = __float2bfloat16(v);
    g_xph[p * C + ci] = h;
    g_xpl[p * C + ci] = __float2bfloat16(v - __bfloat162float(h));
}

// w [co][ci][tap] f32 -> [co][tap*256+ci] bf16 hi/lo (co padded with zeros)
__global__ void wtrans_kernel(const float* __restrict__ src,
                              __nv_bfloat16* __restrict__ dh,
                              __nv_bfloat16* __restrict__ dl,
                              int coutReal) {
    __shared__ float s[KTOT];
    int co = blockIdx.x;
    int tid = threadIdx.x;
    if (co < coutReal)
        for (int k = tid; k < KTOT; k += 256) s[k] = src[co * KTOT + k];
    __syncthreads();
    for (int k = tid; k < KTOT; k += 256) {
        float v = (co < coutReal) ? s[(k & 255) * KTAPS + (k >> 8)] : 0.0f;
        __nv_bfloat16 h = __float2bfloat16(v);
        dh[co * KTOT + k] = h;
        dl[co * KTOT + k] = __float2bfloat16(v - __bfloat162float(h));
    }
}

// ---------------- deformable im2col (f32 gather -> bf16 hi/lo col) ----------------
__global__ void col_build_kernel() {
    int n = blockIdx.x;
    int k = blockIdx.y;
    int tid = threadIdx.x;

    int t = n / 576;
    int r = n - t * 576;
    int h = r / 24;
    int w = r - h * 24;

    float offT = g_offs[n * 81 + k * 3 + 0];
    float offH = g_offs[n * 81 + k * 3 + 1];
    float offW = g_offs[n * 81 + k * 3 + 2];

    float pt = (float)t + (float)(k / 9 - 1) + offT;
    float ph = (float)h + (float)((k / 3) % 3 - 1) + offH;
    float pw = (float)w + (float)(k % 3 - 1) + offW;

    float ft = floorf(pt), fh = floorf(ph), fw = floorf(pw);
    float at = pt - ft, ah = ph - fh, aw = pw - fw;
    int it = (int)ft, ih = (int)fh, iw = (int)fw;

    float ax = 0.f, ay = 0.f, az = 0.f, awv = 0.f;
    #pragma unroll
    for (int dt = 0; dt < 2; dt++) {
        int tt = it + dt;
        float wt = dt ? at : (1.0f - at);
        bool vt = (tt >= 0) && (tt < Tdim);
        int tc = min(max(tt, 0), Tdim - 1);
        #pragma unroll
        for (int dh = 0; dh < 2; dh++) {
            int hh = ih + dh;
            float wh = dh ? ah : (1.0f - ah);
            bool vh = (hh >= 0) && (hh < Hdim);
            int hc = min(max(hh, 0), Hdim - 1);
            #pragma unroll
            for (int dw = 0; dw < 2; dw++) {
                int ww_ = iw + dw;
                float wwf = dw ? aw : (1.0f - aw);
                bool vw = (ww_ >= 0) && (ww_ < Wdim);
                int wc = min(max(ww_, 0), Wdim - 1);
                float wgt = wt * wh * wwf;
                if (!(vt && vh && vw)) wgt = 0.0f;
                int pp = ((tc + 1) * HP + (hc + 1)) * WP + (wc + 1);
                const float4 v = *(const float4*)&g_xpad[pp * C + tid * 4];
                ax += wgt * v.x; ay += wgt * v.y; az += wgt * v.z; awv += wgt * v.w;
            }
        }
    }
    size_t o = ((size_t)n * KTAPS + k) * C + tid * 4;
    __nv_bfloat16 hx = __float2bfloat16(ax), hy = __float2bfloat16(ay);
    __nv_bfloat16 hz = __float2bfloat16(az), hw = __float2bfloat16(awv);
    ushort4 hv = make_ushort4(*(unsigned short*)&hx, *(unsigned short*)&hy,
                              *(unsigned short*)&hz, *(unsigned short*)&hw);
    *(ushort4*)&g_colh[o] = hv;
    __nv_bfloat16 lx = __float2bfloat16(ax - __bfloat162float(hx));
    __nv_bfloat16 ly = __float2bfloat16(ay - __bfloat162float(hy));
    __nv_bfloat16 lz = __float2bfloat16(az - __bfloat162float(hz));
    __nv_bfloat16 lw = __float2bfloat16(awv - __bfloat162float(hw));
    ushort4 lv = make_ushort4(*(unsigned short*)&lx, *(unsigned short*)&ly,
                              *(unsigned short*)&lz, *(unsigned short*)&lw);
    *(ushort4*)&g_coll[o] = lv;
}

// ---------------- mma.sync GEMM: D[M=4608, N] = A * B^T (bf16x3) ----------------
// AMODE 0: A rows = padded features (tap-shifted). AMODE 1: A rows = col (stride KTOT).
// EPI 0: relu(acc+bias) -> bf16 hi/lo padded feature buffers.
// EPI 1: acc+bias -> f32 offs [n][81] (guard co < 81).
// EPI 2: acc+bias -> f32 out [co][n].
template<int AMODE, int EPI>
__global__ __launch_bounds__(256, 1) void tgemm(
    const __nv_bfloat16* __restrict__ Ah, const __nv_bfloat16* __restrict__ Al,
    const __nv_bfloat16* __restrict__ Bh, const __nv_bfloat16* __restrict__ Bl,
    const float* __restrict__ bias,
    float* __restrict__ DstF,
    __nv_bfloat16* __restrict__ DstH, __nv_bfloat16* __restrict__ DstL)
{
    extern __shared__ __align__(1024) char dsm[];
    const u32 smem0 = smem_u32(dsm);

    const int tid = threadIdx.x;
    const int wid = tid >> 5, lane = tid & 31;
    const int bm0 = blockIdx.x * BM, bn0 = blockIdx.y * BN;

    // ---- loader mapping: each thread: rows (tid>>2) and (tid>>2)+64, 16B chunk kg = tid&3
    const int lrow0 = tid >> 2, lrow1 = lrow0 + 64;
    const int lkg = tid & 3;
    const u32 dst0 = swofs((u32)lrow0, (u32)lkg);
    const u32 dst1 = swofs((u32)lrow1, (u32)lkg);
    const int aBase0 = (AMODE == 0) ? pidx(bm0 + lrow0) * C : (bm0 + lrow0) * KTOT;
    const int aBase1 = (AMODE == 0) ? pidx(bm0 + lrow1) * C : (bm0 + lrow1) * KTOT;
    const int bBase0 = (bn0 + lrow0) * KTOT;
    const int bBase1 = (bn0 + lrow1) * KTOT;

    auto issue = [&](int ch) {
        const int k0 = ch * KC;
        int aoff;
        if (AMODE == 0) aoff = c_shift[k0 >> 8] * C + (k0 & 255) + lkg * 8;
        else            aoff = k0 + lkg * 8;
        const int boff = k0 + lkg * 8;
        const u32 sb = smem0 + (ch & 1) * STAGE_BYTES;
        CPASYNC(sb + dst0,          Ah + aBase0 + aoff);
        CPASYNC(sb + dst1,          Ah + aBase1 + aoff);
        CPASYNC(sb + 8192 + dst0,   Al + aBase0 + aoff);
        CPASYNC(sb + 8192 + dst1,   Al + aBase1 + aoff);
        CPASYNC(sb + 16384 + dst0,  Bh + bBase0 + boff);
        CPASYNC(sb + 16384 + dst1,  Bh + bBase1 + boff);
        CPASYNC(sb + 24576 + dst0,  Bl + bBase0 + boff);
        CPASYNC(sb + 24576 + dst1,  Bl + bBase1 + boff);
        CPCOMMIT();
    };

    // ---- compute mapping
    const int mwarp = wid & 1;          // 64-row half
    const int nwarp = wid >> 1;         // 32-col quarter
    const int laneA_row = (lane & 7) + ((lane >> 3) & 1) * 8;
    const int laneA_kg  = lane >> 4;
    const int laneB_row = (lane & 7) + ((lane >> 4) & 1) * 8;
    const int laneB_kg  = (lane >> 3) & 1;

    float acc[4][4][4];
    #pragma unroll
    for (int i = 0; i < 4; i++)
        #pragma unroll
        for (int j = 0; j < 4; j++)
            #pragma unroll
            for (int q = 0; q < 4; q++) acc[i][j][q] = 0.0f;

    issue(0);

    for (int ch = 0; ch < NCH; ch++) {
        if (ch + 1 < NCH) { issue(ch + 1); CPWAIT(1); }
        else              { CPWAIT(0); }
        __syncthreads();

        const u32 sb = smem0 + (ch & 1) * STAGE_BYTES;
        #pragma unroll
        for (int k16 = 0; k16 < 2; k16++) {
            u32 ah[4][4], al[4][4], bh[2][4], bl[2][4];
            #pragma unroll
            for (int mt = 0; mt < 4; mt++) {
                u32 row = mwarp * 64 + mt * 16 + laneA_row;
                u32 addr = sb + swofs(row, k16 * 2 + laneA_kg);
                LDM4(ah[mt], addr);
                LDM4(al[mt], addr + 8192);
            }
            #pragma unroll
            for (int ng = 0; ng < 2; ng++) {
                u32 row = nwarp * 32 + ng * 16 + laneB_row;
                u32 addr = sb + 16384 + swofs(row, k16 * 2 + laneB_kg);
                LDM4(bh[ng], addr);
                LDM4(bl[ng], addr + 8192);
            }
            #pragma unroll
            for (int mt = 0; mt < 4; mt++)
                #pragma unroll
                for (int n8 = 0; n8 < 4; n8++) {
                    const u32* ph = &bh[n8 >> 1][(n8 & 1) * 2];
                    const u32* pl = &bl[n8 >> 1][(n8 & 1) * 2];
                    MMA(acc[mt][n8], ah[mt], ph[0], ph[1]);
                    MMA(acc[mt][n8], ah[mt], pl[0], pl[1]);
                    MMA(acc[mt][n8], al[mt], ph[0], ph[1]);
                }
        }
        __syncthreads();
    }

    // ---- epilogue (c-frag: rows lane>>2 and +8, cols (lane&3)*2 + {0,1})
    const int r0 = lane >> 2;
    const int c0 = (lane & 3) * 2;
    #pragma unroll
    for (int mt = 0; mt < 4; mt++) {
        const int mA = bm0 + mwarp * 64 + mt * 16 + r0;
        const int mB = mA + 8;
        int pA = 0, pB = 0;
        if (EPI == 0) { pA = pidx(mA) * C; pB = pidx(mB) * C; }
        #pragma unroll
        for (int n8 = 0; n8 < 4; n8++) {
            const int gn = bn0 + nwarp * 32 + n8 * 8 + c0;
            const float* d = acc[mt][n8];
            if (EPI == 0) {
                const float b0 = bias[gn], b1 = bias[gn + 1];
                float v0 = fmaxf(d[0] + b0, 0.f), v1 = fmaxf(d[1] + b1, 0.f);
                float v2 = fmaxf(d[2] + b0, 0.f), v3 = fmaxf(d[3] + b1, 0.f);
                __nv_bfloat16 h0 = __float2bfloat16(v0), h1 = __float2bfloat16(v1);
                __nv_bfloat16 h2 = __float2bfloat16(v2), h3 = __float2bfloat16(v3);
                __nv_bfloat162 hp0; hp0.x = h0; hp0.y = h1;
                __nv_bfloat162 hp1; hp1.x = h2; hp1.y = h3;
                *(__nv_bfloat162*)&DstH[pA + gn] = hp0;
                *(__nv_bfloat162*)&DstH[pB + gn] = hp1;
                __nv_bfloat162 lp0, lp1;
                lp0.x = __float2bfloat16(v0 - __bfloat162float(h0));
                lp0.y = __float2bfloat16(v1 - __bfloat162float(h1));
                lp1.x = __float2bfloat16(v2 - __bfloat162float(h2));
                lp1.y = __float2bfloat16(v3 - __bfloat162float(h3));
                *(__nv_bfloat162*)&DstL[pA + gn] = lp0;
                *(__nv_bfloat162*)&DstL[pB + gn] = lp1;
            } else if (EPI == 1) {
                if (gn < 81) {
                    DstF[mA * 81 + gn] = d[0] + bias[gn];
                    DstF[mB * 81 + gn] = d[2] + bias[gn];
                }
                if (gn + 1 < 81) {
                    DstF[mA * 81 + gn + 1] = d[1] + bias[gn + 1];
                    DstF[mB * 81 + gn + 1] = d[3] + bias[gn + 1];
                }
            } else {
                const float b0 = bias[gn], b1 = bias[gn + 1];
                DstF[gn * NSP + mA]       = d[0] + b0;
                DstF[(gn + 1) * NSP + mA] = d[1] + b1;
                DstF[gn * NSP + mB]       = d[2] + b0;
                DstF[(gn + 1) * NSP + mB] = d[3] + b1;
            }
        }
    }
}

// ---------------- launch ----------------
extern "C" void kernel_launch(void* const* d_in, const int* in_sizes, int n_in,
                              void* d_out, int out_size)
{
    const float* x   = (const float*)d_in[0];
    const float* l1w = (const float*)d_in[1];
    const float* l1b = (const float*)d_in[2];
    const float* l2w = (const float*)d_in[3];
    const float* l2b = (const float*)d_in[4];
    const float* l3w = (const float*)d_in[5];
    const float* l3b = (const float*)d_in[6];
    const float* dw  = (const float*)d_in[7];
    const float* db  = (const float*)d_in[8];
    const float* cw  = (const float*)d_in[9];
    const float* cb  = (const float*)d_in[10];
    float* out = (float*)d_out;

    float *xpad, *offs;
    __nv_bfloat16 *xph, *xpl, *fhA, *flA, *fhB, *flB, *colh, *coll;
    __nv_bfloat16 *w1h, *w1l, *w2h, *w2l, *w3h, *w3l, *wch, *wcl, *wdh, *wdl;
    cudaGetSymbolAddress((void**)&xpad, g_xpad);
    cudaGetSymbolAddress((void**)&offs, g_offs);
    cudaGetSymbolAddress((void**)&xph, g_xph);  cudaGetSymbolAddress((void**)&xpl, g_xpl);
    cudaGetSymbolAddress((void**)&fhA, g_fhA);  cudaGetSymbolAddress((void**)&flA, g_flA);
    cudaGetSymbolAddress((void**)&fhB, g_fhB);  cudaGetSymbolAddress((void**)&flB, g_flB);
    cudaGetSymbolAddress((void**)&colh, g_colh); cudaGetSymbolAddress((void**)&coll, g_coll);
    cudaGetSymbolAddress((void**)&w1h, g_w1h);  cudaGetSymbolAddress((void**)&w1l, g_w1l);
    cudaGetSymbolAddress((void**)&w2h, g_w2h);  cudaGetSymbolAddress((void**)&w2l, g_w2l);
    cudaGetSymbolAddress((void**)&w3h, g_w3h);  cudaGetSymbolAddress((void**)&w3l, g_w3l);
    cudaGetSymbolAddress((void**)&wch, g_wch);  cudaGetSymbolAddress((void**)&wcl, g_wcl);
    cudaGetSymbolAddress((void**)&wdh, g_wdh);  cudaGetSymbolAddress((void**)&wdl, g_wdl);

    cudaFuncSetAttribute(tgemm<0, 0>, cudaFuncAttributeMaxDynamicSharedMemorySize, DSMEM_BYTES);
    cudaFuncSetAttribute(tgemm<0, 1>, cudaFuncAttributeMaxDynamicSharedMemorySize, DSMEM_BYTES);
    cudaFuncSetAttribute(tgemm<1, 2>, cudaFuncAttributeMaxDynamicSharedMemorySize, DSMEM_BYTES);

    const int NF32 = NPADS * C / 2;      // u64 count for f32 padded buffer
    const int NBF  = NPADS * C / 4;      // u64 count for bf16 padded buffer
    zero8<<<432, 256>>>((u64*)xpad, NF32);
    zero8<<<432, 256>>>((u64*)xph, NBF);
    zero8<<<432, 256>>>((u64*)xpl, NBF);
    zero8<<<432, 256>>>((u64*)fhA, NBF);
    zero8<<<432, 256>>>((u64*)flA, NBF);
    zero8<<<432, 256>>>((u64*)fhB, NBF);
    zero8<<<432, 256>>>((u64*)flB, NBF);

    transpose_x_kernel<<<NSP, 256>>>(x);
    wtrans_kernel<<<256, 256>>>(l1w, w1h, w1l, 256);
    wtrans_kernel<<<256, 256>>>(l2w, w2h, w2l, 256);
    wtrans_kernel<<<256, 256>>>(l3w, w3h, w3l, 256);
    wtrans_kernel<<<128, 256>>>(dw,  wdh, wdl, 81);
    wtrans_kernel<<<256, 256>>>(cw,  wch, wcl, 256);

    dim3 gBig(NSP / BM, 2), gOff(NSP / BM, 1);
    // conv1: xpad -> fA
    tgemm<0, 0><<<gBig, 256, DSMEM_BYTES>>>(xph, xpl, w1h, w1l, l1b, nullptr, fhA, flA);
    // conv2: fA -> fB
    tgemm<0, 0><<<gBig, 256, DSMEM_BYTES>>>(fhA, flA, w2h, w2l, l2b, nullptr, fhB, flB);
    // conv3: fB -> fA
    tgemm<0, 0><<<gBig, 256, DSMEM_BYTES>>>(fhB, flB, w3h, w3l, l3b, nullptr, fhA, flA);
    // offsets conv: fA -> offs
    tgemm<0, 1><<<gOff, 256, DSMEM_BYTES>>>(fhA, flA, wdh, wdl, db, offs, nullptr, nullptr);
    // deformable im2col
    col_build_kernel<<<dim3(NSP, KTAPS), 64>>>();
    // deformable conv: col -> out (NCDHW)
    tgemm<1, 2><<<gBig, 256, DSMEM_BYTES>>>(colh, coll, wch, wcl, cb, out, nullptr, nullptr);
}

// round 7
// speedup vs baseline: 3.5388x; 1.7325x over previous
#include <cuda_runtime.h>
#include <cuda_bf16.h>
#include <cstdint>

typedef unsigned int u32;
typedef unsigned long long u64;

// ---------------- problem constants ----------------
#define Tdim 8
#define Hdim 24
#define Wdim 24
#define NSP  4608        // 8*24*24
#define HP   26
#define WP   26
#define NPADS 6760       // 10*26*26
#define C    256
#define KTAPS 27
#define KTOT 6912        // 27*256
#define KC   32          // k per chunk
#define NCH  216         // KTOT/KC
#define BM   64          // rows per CTA  -> grid 72 x (128/BNT): 144 CTAs

// ---------------- static device scratch ----------------
__device__ float g_xpad[NPADS * C];
__device__ __nv_bfloat16 g_xph[NPADS * C], g_xpl[NPADS * C];
__device__ __nv_bfloat16 g_fhA[NPADS * C], g_flA[NPADS * C];
__device__ __nv_bfloat16 g_fhB[NPADS * C], g_flB[NPADS * C];
__device__ float g_offs[NSP * 81];
__device__ __nv_bfloat16 g_colh[(size_t)NSP * KTOT], g_coll[(size_t)NSP * KTOT];
__device__ __nv_bfloat16 g_w1h[C * KTOT], g_w1l[C * KTOT];
__device__ __nv_bfloat16 g_w2h[C * KTOT], g_w2l[C * KTOT];
__device__ __nv_bfloat16 g_w3h[C * KTOT], g_w3l[C * KTOT];
__device__ __nv_bfloat16 g_wch[C * KTOT], g_wcl[C * KTOT];
__device__ __nv_bfloat16 g_wdh[128 * KTOT], g_wdl[128 * KTOT];

// tap spatial shift in padded space: ((kt-1)*HP + (kh-1))*WP + (kw-1)
__constant__ int c_shift[27] = {
  -703, -702, -701, -677, -676, -675, -651, -650, -649,
   -27,  -26,  -25,   -1,    0,    1,   25,   26,   27,
   649,  650,  651,  675,  676,  677,  701,  702,  703 };

// ---------------- helpers ----------------
__device__ __forceinline__ int pidx(int n) {
    int t = n / 576;
    int r = n - t * 576;
    int h = r / 24;
    int w = r - h * 24;
    return ((t + 1) * HP + (h + 1)) * WP + (w + 1);
}

__device__ __forceinline__ u32 smem_u32(const void* p) {
    u32 a;
    asm("{ .reg .u64 t; cvta.to.shared.u64 t, %1; cvt.u32.u64 %0, t; }" : "=r"(a) : "l"(p));
    return a;
}

// smem tile layout (rows x 32k bf16): two consecutive rows share a 128B pair
// (8 x 16B chunks). Chunk c = (row&1)*4 + kg, XOR-permuted by pair index.
// Bijective; ldmatrix 8x8 matrices hit 8 distinct 16B slots (verified R5).
__device__ __forceinline__ u32 swofs(u32 row, u32 kg) {
    return ((row >> 1) << 7) + (((((row & 1) << 2) + kg) ^ ((row >> 1) & 7)) << 4);
}

#define CPASYNC(dst, src) \
    asm volatile("cp.async.cg.shared.global [%0], [%1], 16;" :: "r"(dst), "l"(src))
#define CPCOMMIT() asm volatile("cp.async.commit_group;" ::: "memory")
#define CPWAIT(n)  asm volatile("cp.async.wait_group %0;" :: "n"(n) : "memory")

#define LDM4(r, a) \
    asm volatile("ldmatrix.sync.aligned.m8n8.x4.shared.b16 {%0,%1,%2,%3}, [%4];" \
        : "=r"((r)[0]), "=r"((r)[1]), "=r"((r)[2]), "=r"((r)[3]) : "r"(a))

#define MMA(d, a, b0, b1) \
    asm volatile("mma.sync.aligned.m16n8k16.row.col.f32.bf16.bf16.f32 " \
        "{%0,%1,%2,%3}, {%4,%5,%6,%7}, {%8,%9}, {%0,%1,%2,%3};" \
        : "+f"((d)[0]), "+f"((d)[1]), "+f"((d)[2]), "+f"((d)[3]) \
        : "r"((a)[0]), "r"((a)[1]), "r"((a)[2]), "r"((a)[3]), "r"(b0), "r"(b1))

// ---------------- utility kernels ----------------
// one launch zeroing every padded buffer (borders must be 0; interiors are
// fully overwritten each run)
__global__ void zero_all() {
    const int gid = blockIdx.x * blockDim.x + threadIdx.x;
    const int stride = gridDim.x * blockDim.x;
    const int n64b = NPADS * C / 4;   // u64 count for a bf16 buffer
    const int n64f = NPADS * C / 2;   // u64 count for the f32 buffer
    for (int i = gid; i < n64b; i += stride) {
        ((u64*)g_xph)[i] = 0ull; ((u64*)g_xpl)[i] = 0ull;
        ((u64*)g_fhA)[i] = 0ull; ((u64*)g_flA)[i] = 0ull;
        ((u64*)g_fhB)[i] = 0ull; ((u64*)g_flB)[i] = 0ull;
    }
    for (int i = gid; i < n64f; i += stride) ((u64*)g_xpad)[i] = 0ull;
}

// x [ci][n] -> xpad(+bf16 hi/lo) [p(n)][ci]
__global__ void transpose_x_kernel(const float* __restrict__ x) {
    int n = blockIdx.x;
    int ci = threadIdx.x;
    int p = pidx(n);
    float v = x[ci * NSP + n];
    g_xpad[p * C + ci] = v;
    __nv_bfloat16 h = __float2bfloat16(v);
    g_xph[p * C + ci] = h;
    g_xpl[p * C + ci] = __float2bfloat16(v - __bfloat162float(h));
}

// w [co][ci][tap] f32 -> [co][tap*256+ci] bf16 hi/lo (co padded with zeros)
__global__ void wtrans_kernel(const float* __restrict__ src,
                              __nv_bfloat16* __restrict__ dh,
                              __nv_bfloat16* __restrict__ dl,
                              int coutReal) {
    __shared__ float s[KTOT];
    int co = blockIdx.x;
    int tid = threadIdx.x;
    if (co < coutReal)
        for (int k = tid; k < KTOT; k += 256) s[k] = src[co * KTOT + k];
    __syncthreads();
    for (int k = tid; k < KTOT; k += 256) {
        float v = (co < coutReal) ? s[(k & 255) * KTAPS + (k >> 8)] : 0.0f;
        __nv_bfloat16 h = __float2bfloat16(v);
        dh[co * KTOT + k] = h;
        dl[co * KTOT + k] = __float2bfloat16(v - __bfloat162float(h));
    }
}

// ---------------- deformable im2col (f32 gather -> bf16 hi/lo col) ----------------
__global__ void col_build_kernel() {
    int n = blockIdx.x;
    int k = blockIdx.y;
    int tid = threadIdx.x;

    int t = n / 576;
    int r = n - t * 576;
    int h = r / 24;
    int w = r - h * 24;

    float offT = g_offs[n * 81 + k * 3 + 0];
    float offH = g_offs[n * 81 + k * 3 + 1];
    float offW = g_offs[n * 81 + k * 3 + 2];

    float pt = (float)t + (float)(k / 9 - 1) + offT;
    float ph = (float)h + (float)((k / 3) % 3 - 1) + offH;
    float pw = (float)w + (float)(k % 3 - 1) + offW;

    float ft = floorf(pt), fh = floorf(ph), fw = floorf(pw);
    float at = pt - ft, ah = ph - fh, aw = pw - fw;
    int it = (int)ft, ih = (int)fh, iw = (int)fw;

    float ax = 0.f, ay = 0.f, az = 0.f, awv = 0.f;
    #pragma unroll
    for (int dt = 0; dt < 2; dt++) {
        int tt = it + dt;
        float wt = dt ? at : (1.0f - at);
        bool vt = (tt >= 0) && (tt < Tdim);
        int tc = min(max(tt, 0), Tdim - 1);
        #pragma unroll
        for (int dh = 0; dh < 2; dh++) {
            int hh = ih + dh;
            float wh = dh ? ah : (1.0f - ah);
            bool vh = (hh >= 0) && (hh < Hdim);
            int hc = min(max(hh, 0), Hdim - 1);
            #pragma unroll
            for (int dw = 0; dw < 2; dw++) {
                int ww_ = iw + dw;
                float wwf = dw ? aw : (1.0f - aw);
                bool vw = (ww_ >= 0) && (ww_ < Wdim);
                int wc = min(max(ww_, 0), Wdim - 1);
                float wgt = wt * wh * wwf;
                if (!(vt && vh && vw)) wgt = 0.0f;
                int pp = ((tc + 1) * HP + (hc + 1)) * WP + (wc + 1);
                const float4 v = *(const float4*)&g_xpad[pp * C + tid * 4];
                ax += wgt * v.x; ay += wgt * v.y; az += wgt * v.z; awv += wgt * v.w;
            }
        }
    }
    size_t o = ((size_t)n * KTAPS + k) * C + tid * 4;
    __nv_bfloat16 hx = __float2bfloat16(ax), hy = __float2bfloat16(ay);
    __nv_bfloat16 hz = __float2bfloat16(az), hw = __float2bfloat16(awv);
    ushort4 hv = make_ushort4(*(unsigned short*)&hx, *(unsigned short*)&hy,
                              *(unsigned short*)&hz, *(unsigned short*)&hw);
    *(ushort4*)&g_colh[o] = hv;
    __nv_bfloat16 lx = __float2bfloat16(ax - __bfloat162float(hx));
    __nv_bfloat16 ly = __float2bfloat16(ay - __bfloat162float(hy));
    __nv_bfloat16 lz = __float2bfloat16(az - __bfloat162float(hz));
    __nv_bfloat16 lw = __float2bfloat16(awv - __bfloat162float(hw));
    ushort4 lv = make_ushort4(*(unsigned short*)&lx, *(unsigned short*)&ly,
                              *(unsigned short*)&lz, *(unsigned short*)&lw);
    *(ushort4*)&g_coll[o] = lv;
}

// ---------------- mma.sync GEMM: D[M=4608, N] = A * B^T (bf16x3) ----------------
// BM=64 rows/CTA, BNT cols/CTA (128 or 64). 8 warps: mwarp=wid&1 (32 rows),
// nwarp=wid>>1 (BNT/4 cols). 4-stage cp.async pipeline, 1 sync per chunk.
// AMODE 0: A rows = padded features (tap-shifted). AMODE 1: A rows = col.
// EPI 0: relu(acc+bias) -> bf16 hi/lo padded feature buffers.
// EPI 1: acc+bias -> f32 offs [n][81] (guard co < 81).
// EPI 2: acc+bias -> f32 out [co][n].
template<int BNT, int AMODE, int EPI>
__global__ __launch_bounds__(256, 1) void tgemm(
    const __nv_bfloat16* __restrict__ Ah, const __nv_bfloat16* __restrict__ Al,
    const __nv_bfloat16* __restrict__ Bh, const __nv_bfloat16* __restrict__ Bl,
    const float* __restrict__ bias,
    float* __restrict__ DstF,
    __nv_bfloat16* __restrict__ DstH, __nv_bfloat16* __restrict__ DstL)
{
    constexpr int NT = BNT / 64;           // n16 tiles per warp (2 or 1)
    constexpr int ASZ = 4096;              // 64 x 32 bf16
    constexpr int BSZ = BNT * 64;          // BNT x 32 bf16
    constexpr int STAGE = 2 * ASZ + 2 * BSZ;
    constexpr int S = 4;

    extern __shared__ __align__(1024) char dsm[];
    const u32 smem0 = smem_u32(dsm);

    const int tid = threadIdx.x;
    const int wid = tid >> 5, lane = tid & 31;
    const int bm0 = blockIdx.x * BM, bn0 = blockIdx.y * BNT;

    // ---- loader mapping: A: 64 rows x 4 chunks (1 op/thread/tile);
    //      B: rows tid>>2 (+64 for BNT=128), chunk tid&3
    const int arow = tid >> 2;
    const int akg  = tid & 3;
    const u32 dstA = swofs((u32)arow, (u32)akg);
    const int aBase = (AMODE == 0) ? pidx(bm0 + arow) * C : (bm0 + arow) * KTOT;
    const u32 dstB0 = dstA;
    const int bBase0 = (bn0 + arow) * KTOT;
    const u32 dstB1 = swofs((u32)(arow + 64), (u32)akg);
    const int bBase1 = (bn0 + arow + 64) * KTOT;

    auto issue = [&](int ch) {
        const int k0 = ch * KC;
        int aoff;
        if (AMODE == 0) aoff = c_shift[k0 >> 8] * C + (k0 & 255) + akg * 8;
        else            aoff = k0 + akg * 8;
        const int boff = k0 + akg * 8;
        const u32 sb = smem0 + (u32)(ch & (S - 1)) * STAGE;
        CPASYNC(sb + dstA,                    Ah + aBase + aoff);
        CPASYNC(sb + ASZ + dstA,              Al + aBase + aoff);
        CPASYNC(sb + 2 * ASZ + dstB0,         Bh + bBase0 + boff);
        CPASYNC(sb + 2 * ASZ + BSZ + dstB0,   Bl + bBase0 + boff);
        if (BNT == 128) {
            CPASYNC(sb + 2 * ASZ + dstB1,       Bh + bBase1 + boff);
            CPASYNC(sb + 2 * ASZ + BSZ + dstB1, Bl + bBase1 + boff);
        }
        CPCOMMIT();
    };

    // ---- compute mapping (lane maps verified in R5)
    const int mwarp = wid & 1;
    const int nwarp = wid >> 1;
    const int laneA_row = (lane & 7) + ((lane >> 3) & 1) * 8;
    const int laneA_kg  = lane >> 4;
    const int laneB_row = (lane & 7) + ((lane >> 4) & 1) * 8;
    const int laneB_kg  = (lane >> 3) & 1;

    float acc[2][2 * NT][4];
    #pragma unroll
    for (int i = 0; i < 2; i++)
        #pragma unroll
        for (int j = 0; j < 2 * NT; j++)
            #pragma unroll
            for (int q = 0; q < 4; q++) acc[i][j][q] = 0.0f;

    #pragma unroll
    for (int s = 0; s < S - 1; s++) issue(s);

    for (int ch = 0; ch < NCH; ch++) {
        CPWAIT(S - 2);
        __syncthreads();
        if (ch + S - 1 < NCH) issue(ch + S - 1);
        else CPCOMMIT();                      // keep group count uniform

        const u32 sb = smem0 + (u32)(ch & (S - 1)) * STAGE;
        #pragma unroll
        for (int k16 = 0; k16 < 2; k16++) {
            u32 ah[2][4], al[2][4], bh[NT][4], bl[NT][4];
            #pragma unroll
            for (int mt = 0; mt < 2; mt++) {
                u32 row = mwarp * 32 + mt * 16 + laneA_row;
                u32 addr = sb + swofs(row, k16 * 2 + laneA_kg);
                LDM4(ah[mt], addr);
                LDM4(al[mt], addr + ASZ);
            }
            #pragma unroll
            for (int nt = 0; nt < NT; nt++) {
                u32 row = nwarp * (NT * 16) + nt * 16 + laneB_row;
                u32 addr = sb + 2 * ASZ + swofs(row, k16 * 2 + laneB_kg);
                LDM4(bh[nt], addr);
                LDM4(bl[nt], addr + BSZ);
            }
            #pragma unroll
            for (int mt = 0; mt < 2; mt++)
                #pragma unroll
                for (int n8 = 0; n8 < 2 * NT; n8++) {
                    const u32* ph = &bh[n8 >> 1][(n8 & 1) * 2];
                    const u32* pl = &bl[n8 >> 1][(n8 & 1) * 2];
                    MMA(acc[mt][n8], ah[mt], ph[0], ph[1]);
                    MMA(acc[mt][n8], ah[mt], pl[0], pl[1]);
                    MMA(acc[mt][n8], al[mt], ph[0], ph[1]);
                }
        }
    }

    // ---- epilogue (c-frag: rows lane>>2 and +8, cols (lane&3)*2 + {0,1})
    const int r0 = lane >> 2;
    const int c0 = (lane & 3) * 2;
    #pragma unroll
    for (int mt = 0; mt < 2; mt++) {
        const int mA = bm0 + mwarp * 32 + mt * 16 + r0;
        const int mB = mA + 8;
        int pA = 0, pB = 0;
        if (EPI == 0) { pA = pidx(mA) * C; pB = pidx(mB) * C; }
        #pragma unroll
        for (int n8 = 0; n8 < 2 * NT; n8++) {
            const int gn = bn0 + nwarp * (NT * 16) + n8 * 8 + c0;
            const float* d = acc[mt][n8];
            if (EPI == 0) {
                const float b0 = bias[gn], b1 = bias[gn + 1];
                float v0 = fmaxf(d[0] + b0, 0.f), v1 = fmaxf(d[1] + b1, 0.f);
                float v2 = fmaxf(d[2] + b0, 0.f), v3 = fmaxf(d[3] + b1, 0.f);
                __nv_bfloat16 h0 = __float2bfloat16(v0), h1 = __float2bfloat16(v1);
                __nv_bfloat16 h2 = __float2bfloat16(v2), h3 = __float2bfloat16(v3);
                __nv_bfloat162 hp0; hp0.x = h0; hp0.y = h1;
                __nv_bfloat162 hp1; hp1.x = h2; hp1.y = h3;
                *(__nv_bfloat162*)&DstH[pA + gn] = hp0;
                *(__nv_bfloat162*)&DstH[pB + gn] = hp1;
                __nv_bfloat162 lp0, lp1;
                lp0.x = __float2bfloat16(v0 - __bfloat162float(h0));
                lp0.y = __float2bfloat16(v1 - __bfloat162float(h1));
                lp1.x = __float2bfloat16(v2 - __bfloat162float(h2));
                lp1.y = __float2bfloat16(v3 - __bfloat162float(h3));
                *(__nv_bfloat162*)&DstL[pA + gn] = lp0;
                *(__nv_bfloat162*)&DstL[pB + gn] = lp1;
            } else if (EPI == 1) {
                if (gn < 81) {
                    DstF[mA * 81 + gn] = d[0] + bias[gn];
                    DstF[mB * 81 + gn] = d[2] + bias[gn];
                }
                if (gn + 1 < 81) {
                    DstF[mA * 81 + gn + 1] = d[1] + bias[gn + 1];
                    DstF[mB * 81 + gn + 1] = d[3] + bias[gn + 1];
                }
            } else {
                const float b0 = bias[gn], b1 = bias[gn + 1];
                DstF[gn * NSP + mA]       = d[0] + b0;
                DstF[(gn + 1) * NSP + mA] = d[1] + b1;
                DstF[gn * NSP + mB]       = d[2] + b0;
                DstF[(gn + 1) * NSP + mB] = d[3] + b1;
            }
        }
    }
}

// ---------------- launch ----------------
extern "C" void kernel_launch(void* const* d_in, const int* in_sizes, int n_in,
                              void* d_out, int out_size)
{
    const float* x   = (const float*)d_in[0];
    const float* l1w = (const float*)d_in[1];
    const float* l1b = (const float*)d_in[2];
    const float* l2w = (const float*)d_in[3];
    const float* l2b = (const float*)d_in[4];
    const float* l3w = (const float*)d_in[5];
    const float* l3b = (const float*)d_in[6];
    const float* dw  = (const float*)d_in[7];
    const float* db  = (const float*)d_in[8];
    const float* cw  = (const float*)d_in[9];
    const float* cb  = (const float*)d_in[10];
    float* out = (float*)d_out;

    float *offs;
    __nv_bfloat16 *xph, *xpl, *fhA, *flA, *fhB, *flB, *colh, *coll;
    __nv_bfloat16 *w1h, *w1l, *w2h, *w2l, *w3h, *w3l, *wch, *wcl, *wdh, *wdl;
    cudaGetSymbolAddress((void**)&offs, g_offs);
    cudaGetSymbolAddress((void**)&xph, g_xph);  cudaGetSymbolAddress((void**)&xpl, g_xpl);
    cudaGetSymbolAddress((void**)&fhA, g_fhA);  cudaGetSymbolAddress((void**)&flA, g_flA);
    cudaGetSymbolAddress((void**)&fhB, g_fhB);  cudaGetSymbolAddress((void**)&flB, g_flB);
    cudaGetSymbolAddress((void**)&colh, g_colh); cudaGetSymbolAddress((void**)&coll, g_coll);
    cudaGetSymbolAddress((void**)&w1h, g_w1h);  cudaGetSymbolAddress((void**)&w1l, g_w1l);
    cudaGetSymbolAddress((void**)&w2h, g_w2h);  cudaGetSymbolAddress((void**)&w2l, g_w2l);
    cudaGetSymbolAddress((void**)&w3h, g_w3h);  cudaGetSymbolAddress((void**)&w3l, g_w3l);
    cudaGetSymbolAddress((void**)&wch, g_wch);  cudaGetSymbolAddress((void**)&wcl, g_wcl);
    cudaGetSymbolAddress((void**)&wdh, g_wdh);  cudaGetSymbolAddress((void**)&wdl, g_wdl);

    const int DS128 = 4 * (2 * 4096 + 2 * 128 * 64);   // 98304
    const int DS64  = 4 * (2 * 4096 + 2 * 64 * 64);    // 65536
    cudaFuncSetAttribute(tgemm<128, 0, 0>, cudaFuncAttributeMaxDynamicSharedMemorySize, DS128);
    cudaFuncSetAttribute(tgemm<64,  0, 1>, cudaFuncAttributeMaxDynamicSharedMemorySize, DS64);
    cudaFuncSetAttribute(tgemm<128, 1, 2>, cudaFuncAttributeMaxDynamicSharedMemorySize, DS128);

    zero_all<<<592, 256>>>();
    transpose_x_kernel<<<NSP, 256>>>(x);
    wtrans_kernel<<<256, 256>>>(l1w, w1h, w1l, 256);
    wtrans_kernel<<<256, 256>>>(l2w, w2h, w2l, 256);
    wtrans_kernel<<<256, 256>>>(l3w, w3h, w3l, 256);
    wtrans_kernel<<<128, 256>>>(dw,  wdh, wdl, 81);
    wtrans_kernel<<<256, 256>>>(cw,  wch, wcl, 256);

    dim3 gBig(NSP / BM, 2);    // 72 x 2 = 144 CTAs (BNT=128)
    dim3 gOff(NSP / BM, 2);    // 72 x 2 = 144 CTAs (BNT=64)
    // conv1: xpad -> fA
    tgemm<128, 0, 0><<<gBig, 256, DS128>>>(xph, xpl, w1h, w1l, l1b, nullptr, fhA, flA);
    // conv2: fA -> fB
    tgemm<128, 0, 0><<<gBig, 256, DS128>>>(fhA, flA, w2h, w2l, l2b, nullptr, fhB, flB);
    // conv3: fB -> fA
    tgemm<128, 0, 0><<<gBig, 256, DS128>>>(fhB, flB, w3h, w3l, l3b, nullptr, fhA, flA);
    // offsets conv: fA -> offs (BNT=64, both column halves)
    tgemm<64, 0, 1><<<gOff, 256, DS64>>>(fhA, flA, wdh, wdl, db, offs, nullptr, nullptr);
    // deformable im2col
    col_build_kernel<<<dim3(NSP, KTAPS), 64>>>();
    // deformable conv: col -> out (NCDHW)
    tgemm<128, 1, 2><<<gBig, 256, DS128>>>(colh, coll, wch, wcl, cb, out, nullptr, nullptr);
}

// round 8
// speedup vs baseline: 3.8330x; 1.0831x over previous
#include <cuda_runtime.h>
#include <cuda_bf16.h>
#include <cstdint>

typedef unsigned int u32;
typedef unsigned long long u64;

// ---------------- problem constants ----------------
#define Tdim 8
#define Hdim 24
#define Wdim 24
#define NSP  4608        // 8*24*24
#define HP   26
#define WP   26
#define NPADS 6760       // 10*26*26
#define C    256
#define KTAPS 27
#define KTOT 6912        // 27*256
#define KC   32          // k per sub-chunk
#define NCH  216         // KTOT/KC
#define NMC  108         // macro chunks (2 sub-chunks each)
#define BM   64          // rows per CTA  -> grid 72 x (128/BNT): 144 CTAs

// ---------------- static device scratch ----------------
__device__ float g_xpad[NPADS * C];
__device__ __nv_bfloat16 g_xph[NPADS * C], g_xpl[NPADS * C];
__device__ __nv_bfloat16 g_fhA[NPADS * C], g_flA[NPADS * C];
__device__ __nv_bfloat16 g_fhB[NPADS * C], g_flB[NPADS * C];
__device__ float g_offs[NSP * 81];
__device__ __nv_bfloat16 g_colh[(size_t)NSP * KTOT], g_coll[(size_t)NSP * KTOT];
__device__ __nv_bfloat16 g_w1h[C * KTOT], g_w1l[C * KTOT];
__device__ __nv_bfloat16 g_w2h[C * KTOT], g_w2l[C * KTOT];
__device__ __nv_bfloat16 g_w3h[C * KTOT], g_w3l[C * KTOT];
__device__ __nv_bfloat16 g_wch[C * KTOT], g_wcl[C * KTOT];
__device__ __nv_bfloat16 g_wdh[128 * KTOT], g_wdl[128 * KTOT];

// tap spatial shift in padded space: ((kt-1)*HP + (kh-1))*WP + (kw-1)
__constant__ int c_shift[27] = {
  -703, -702, -701, -677, -676, -675, -651, -650, -649,
   -27,  -26,  -25,   -1,    0,    1,   25,   26,   27,
   649,  650,  651,  675,  676,  677,  701,  702,  703 };

// ---------------- helpers ----------------
__device__ __forceinline__ int pidx(int n) {
    int t = n / 576;
    int r = n - t * 576;
    int h = r / 24;
    int w = r - h * 24;
    return ((t + 1) * HP + (h + 1)) * WP + (w + 1);
}

__device__ __forceinline__ u32 smem_u32(const void* p) {
    u32 a;
    asm("{ .reg .u64 t; cvta.to.shared.u64 t, %1; cvt.u32.u64 %0, t; }" : "=r"(a) : "l"(p));
    return a;
}

// smem tile layout (rows x 32k bf16): two consecutive rows share a 128B pair
// (8 x 16B chunks). Chunk c = (row&1)*4 + kg, XOR-permuted by pair index.
// Bijective; ldmatrix 8x8 matrices hit 8 distinct 16B slots (verified R5).
__device__ __forceinline__ u32 swofs(u32 row, u32 kg) {
    return ((row >> 1) << 7) + (((((row & 1) << 2) + kg) ^ ((row >> 1) & 7)) << 4);
}

#define CPASYNC(dst, src) \
    asm volatile("cp.async.cg.shared.global [%0], [%1], 16;" :: "r"(dst), "l"(src))
#define CPCOMMIT() asm volatile("cp.async.commit_group;" ::: "memory")
#define CPWAIT(n)  asm volatile("cp.async.wait_group %0;" :: "n"(n) : "memory")

#define LDM4(r, a) \
    asm volatile("ldmatrix.sync.aligned.m8n8.x4.shared.b16 {%0,%1,%2,%3}, [%4];" \
        : "=r"((r)[0]), "=r"((r)[1]), "=r"((r)[2]), "=r"((r)[3]) : "r"(a))

#define MMA(d, a, b0, b1) \
    asm volatile("mma.sync.aligned.m16n8k16.row.col.f32.bf16.bf16.f32 " \
        "{%0,%1,%2,%3}, {%4,%5,%6,%7}, {%8,%9}, {%0,%1,%2,%3};" \
        : "+f"((d)[0]), "+f"((d)[1]), "+f"((d)[2]), "+f"((d)[3]) \
        : "r"((a)[0]), "r"((a)[1]), "r"((a)[2]), "r"((a)[3]), "r"(b0), "r"(b1))

// ---------------- utility kernels ----------------
// zero ONLY the padded border rows of the bf16 feature buffers. Interiors are
// fully rewritten every run; g_xpad borders are never read (gathers clip to
// the interior), so g_xpad needs no zeroing at all.
__global__ void zero_border() {
    int idx = blockIdx.x * blockDim.x + threadIdx.x;
    const int stride = gridDim.x * blockDim.x;
    const int TOT = NPADS * 64;            // 64 u64 per 512B bf16 row
    for (; idx < TOT; idx += stride) {
        int p = idx >> 6;
        int c = idx & 63;
        int t = p / 676;
        int r = p - t * 676;
        int h = r / 26;
        int w = r - h * 26;
        bool border = (t == 0) | (t == 9) | (h == 0) | (h == 25) | (w == 0) | (w == 25);
        if (border) {
            size_t o = (size_t)p * 64 + c;
            ((u64*)g_xph)[o] = 0ull; ((u64*)g_xpl)[o] = 0ull;
            ((u64*)g_fhA)[o] = 0ull; ((u64*)g_flA)[o] = 0ull;
            ((u64*)g_fhB)[o] = 0ull; ((u64*)g_flB)[o] = 0ull;
        }
    }
}

// x [ci][n] -> xpad(+bf16 hi/lo) [p(n)][ci]
__global__ void transpose_x_kernel(const float* __restrict__ x) {
    int n = blockIdx.x;
    int ci = threadIdx.x;
    int p = pidx(n);
    float v = x[ci * NSP + n];
    g_xpad[p * C + ci] = v;
    __nv_bfloat16 h = __float2bfloat16(v);
    g_xph[p * C + ci] = h;
    g_xpl[p * C + ci] = __float2bfloat16(v - __bfloat162float(h));
}

// ALL weight transforms in one launch. w [co][ci][tap] f32 ->
// [co][tap*256+ci] bf16 hi/lo (co zero-padded past coutReal).
// grid = 4*256 (l1,l2,l3,cw) + 128 (dw) = 1152 blocks.
__global__ void wtrans_all(const float* __restrict__ l1w,
                           const float* __restrict__ l2w,
                           const float* __restrict__ l3w,
                           const float* __restrict__ cw,
                           const float* __restrict__ dww) {
    __shared__ float s[KTOT];
    const int bid = blockIdx.x;
    const int tid = threadIdx.x;
    const float* src; __nv_bfloat16 *dh, *dl; int co, coutReal;
    if (bid < 256)       { src = l1w; dh = g_w1h; dl = g_w1l; co = bid;        coutReal = 256; }
    else if (bid < 512)  { src = l2w; dh = g_w2h; dl = g_w2l; co = bid - 256;  coutReal = 256; }
    else if (bid < 768)  { src = l3w; dh = g_w3h; dl = g_w3l; co = bid - 512;  coutReal = 256; }
    else if (bid < 1024) { src = cw;  dh = g_wch; dl = g_wcl; co = bid - 768;  coutReal = 256; }
    else                 { src = dww; dh = g_wdh; dl = g_wdl; co = bid - 1024; coutReal = 81;  }
    if (co < coutReal)
        for (int k = tid; k < KTOT; k += 256) s[k] = src[co * KTOT + k];
    __syncthreads();
    for (int k = tid; k < KTOT; k += 256) {
        float v = (co < coutReal) ? s[(k & 255) * KTAPS + (k >> 8)] : 0.0f;
        __nv_bfloat16 h = __float2bfloat16(v);
        dh[co * KTOT + k] = h;
        dl[co * KTOT + k] = __float2bfloat16(v - __bfloat162float(h));
    }
}

// ---------------- deformable im2col (f32 gather -> bf16 hi/lo col) ----------------
// one block per output voxel n; 256 threads = 4 taps x 64 channel-groups.
// All 27 taps of one voxel share a small neighborhood -> L1 reuse.
__global__ void col_build_kernel() {
    __shared__ float soffs[81];
    const int n = blockIdx.x;
    const int tid = threadIdx.x;
    if (tid < 81) soffs[tid] = g_offs[n * 81 + tid];
    __syncthreads();

    const int t = n / 576;
    const int r = n - t * 576;
    const int h = r / 24;
    const int w = r - h * 24;
    const int ksub = tid >> 6;       // 0..3
    const int cg = tid & 63;         // channel group (4 ch)

    for (int kb = 0; kb < 28; kb += 4) {
        const int k = kb + ksub;
        if (k >= 27) break;

        float pt = (float)t + (float)(k / 9 - 1) + soffs[k * 3 + 0];
        float ph = (float)h + (float)((k / 3) % 3 - 1) + soffs[k * 3 + 1];
        float pw = (float)w + (float)(k % 3 - 1) + soffs[k * 3 + 2];

        float ft = floorf(pt), fh = floorf(ph), fw = floorf(pw);
        float at = pt - ft, ah = ph - fh, aw = pw - fw;
        int it = (int)ft, ih = (int)fh, iw = (int)fw;

        float ax = 0.f, ay = 0.f, az = 0.f, awv = 0.f;
        #pragma unroll
        for (int dt = 0; dt < 2; dt++) {
            int tt = it + dt;
            float wt = dt ? at : (1.0f - at);
            bool vt = (tt >= 0) && (tt < Tdim);
            int tc = min(max(tt, 0), Tdim - 1);
            #pragma unroll
            for (int dh = 0; dh < 2; dh++) {
                int hh = ih + dh;
                float wh = dh ? ah : (1.0f - ah);
                bool vh = (hh >= 0) && (hh < Hdim);
                int hc = min(max(hh, 0), Hdim - 1);
                #pragma unroll
                for (int dw = 0; dw < 2; dw++) {
                    int ww_ = iw + dw;
                    float wwf = dw ? aw : (1.0f - aw);
                    bool vw = (ww_ >= 0) && (ww_ < Wdim);
                    int wc = min(max(ww_, 0), Wdim - 1);
                    float wgt = wt * wh * wwf;
                    if (!(vt && vh && vw)) wgt = 0.0f;
                    int pp = ((tc + 1) * HP + (hc + 1)) * WP + (wc + 1);
                    const float4 v = *(const float4*)&g_xpad[pp * C + cg * 4];
                    ax += wgt * v.x; ay += wgt * v.y; az += wgt * v.z; awv += wgt * v.w;
                }
            }
        }
        size_t o = ((size_t)n * KTAPS + k) * C + cg * 4;
        __nv_bfloat16 hx = __float2bfloat16(ax), hy = __float2bfloat16(ay);
        __nv_bfloat16 hz = __float2bfloat16(az), hw = __float2bfloat16(awv);
        ushort4 hv = make_ushort4(*(unsigned short*)&hx, *(unsigned short*)&hy,
                                  *(unsigned short*)&hz, *(unsigned short*)&hw);
        *(ushort4*)&g_colh[o] = hv;
        __nv_bfloat16 lx = __float2bfloat16(ax - __bfloat162float(hx));
        __nv_bfloat16 ly = __float2bfloat16(ay - __bfloat162float(hy));
        __nv_bfloat16 lz = __float2bfloat16(az - __bfloat162float(hz));
        __nv_bfloat16 lw = __float2bfloat16(awv - __bfloat162float(hw));
        ushort4 lv = make_ushort4(*(unsigned short*)&lx, *(unsigned short*)&ly,
                                  *(unsigned short*)&lz, *(unsigned short*)&lw);
        *(ushort4*)&g_coll[o] = lv;
    }
}

// ---------------- mma.sync GEMM: D[M=4608, N] = A * B^T (bf16x3) ----------------
// BM=64 rows/CTA, BNT cols/CTA (128 or 64). 8 warps: mwarp=wid&1 (32 rows),
// nwarp=wid>>1. 3-stage macro-pipeline, 2 sub-chunks (KC=32) per stage,
// one __syncthreads per macro chunk.
// AMODE 0: A rows = padded features (tap-shifted). AMODE 1: A rows = col.
// EPI 0: relu(acc+bias) -> bf16 hi/lo padded feature buffers.
// EPI 1: acc+bias -> f32 offs [n][81] (guard co < 81).
// EPI 2: acc+bias -> f32 out [co][n].
template<int BNT, int AMODE, int EPI>
__global__ __launch_bounds__(256, 1) void tgemm(
    const __nv_bfloat16* __restrict__ Ah, const __nv_bfloat16* __restrict__ Al,
    const __nv_bfloat16* __restrict__ Bh, const __nv_bfloat16* __restrict__ Bl,
    const float* __restrict__ bias,
    float* __restrict__ DstF,
    __nv_bfloat16* __restrict__ DstH, __nv_bfloat16* __restrict__ DstL)
{
    constexpr int NT = BNT / 64;           // n16 tiles per warp (2 or 1)
    constexpr int ASZ = 4096;              // 64 x 32 bf16
    constexpr int BSZ = BNT * 64;          // BNT x 32 bf16
    constexpr int SUB = 2 * ASZ + 2 * BSZ; // one KC=32 sub-stage
    constexpr int MACRO = 2 * SUB;
    constexpr int S = 3;

    extern __shared__ __align__(1024) char dsm[];
    const u32 smem0 = smem_u32(dsm);

    const int tid = threadIdx.x;
    const int wid = tid >> 5, lane = tid & 31;
    const int bm0 = blockIdx.x * BM, bn0 = blockIdx.y * BNT;

    // ---- loader mapping
    const int arow = tid >> 2;
    const int akg  = tid & 3;
    const u32 dstA = swofs((u32)arow, (u32)akg);
    const int aBase = (AMODE == 0) ? pidx(bm0 + arow) * C : (bm0 + arow) * KTOT;
    const u32 dstB0 = dstA;
    const int bBase0 = (bn0 + arow) * KTOT;
    const u32 dstB1 = swofs((u32)(arow + 64), (u32)akg);
    const int bBase1 = (bn0 + arow + 64) * KTOT;

    auto issue32 = [&](int ch, u32 sb) {
        const int k0 = ch * KC;
        int aoff;
        if (AMODE == 0) aoff = c_shift[k0 >> 8] * C + (k0 & 255) + akg * 8;
        else            aoff = k0 + akg * 8;
        const int boff = k0 + akg * 8;
        CPASYNC(sb + dstA,                    Ah + aBase + aoff);
        CPASYNC(sb + ASZ + dstA,              Al + aBase + aoff);
        CPASYNC(sb + 2 * ASZ + dstB0,         Bh + bBase0 + boff);
        CPASYNC(sb + 2 * ASZ + BSZ + dstB0,   Bl + bBase0 + boff);
        if (BNT == 128) {
            CPASYNC(sb + 2 * ASZ + dstB1,       Bh + bBase1 + boff);
            CPASYNC(sb + 2 * ASZ + BSZ + dstB1, Bl + bBase1 + boff);
        }
    };
    auto issue_macro = [&](int mc) {
        const u32 base = smem0 + (u32)(mc % S) * MACRO;
        issue32(2 * mc,     base);
        issue32(2 * mc + 1, base + SUB);
        CPCOMMIT();
    };

    // ---- compute mapping (lane maps verified in R5)
    const int mwarp = wid & 1;
    const int nwarp = wid >> 1;
    const int laneA_row = (lane & 7) + ((lane >> 3) & 1) * 8;
    const int laneA_kg  = lane >> 4;
    const int laneB_row = (lane & 7) + ((lane >> 4) & 1) * 8;
    const int laneB_kg  = (lane >> 3) & 1;

    float acc[2][2 * NT][4];
    #pragma unroll
    for (int i = 0; i < 2; i++)
        #pragma unroll
        for (int j = 0; j < 2 * NT; j++)
            #pragma unroll
            for (int q = 0; q < 4; q++) acc[i][j][q] = 0.0f;

    #pragma unroll
    for (int s = 0; s < S - 1; s++) issue_macro(s);

    for (int mc = 0; mc < NMC; mc++) {
        CPWAIT(S - 2);
        __syncthreads();
        if (mc + S - 1 < NMC) issue_macro(mc + S - 1);
        else CPCOMMIT();                      // keep group count uniform

        const u32 base = smem0 + (u32)(mc % S) * MACRO;
        #pragma unroll
        for (int sub = 0; sub < 2; sub++) {
            const u32 sb = base + (u32)sub * SUB;
            #pragma unroll
            for (int k16 = 0; k16 < 2; k16++) {
                u32 ah[2][4], al[2][4], bh[NT][4], bl[NT][4];
                #pragma unroll
                for (int mt = 0; mt < 2; mt++) {
                    u32 row = mwarp * 32 + mt * 16 + laneA_row;
                    u32 addr = sb + swofs(row, k16 * 2 + laneA_kg);
                    LDM4(ah[mt], addr);
                    LDM4(al[mt], addr + ASZ);
                }
                #pragma unroll
                for (int nt = 0; nt < NT; nt++) {
                    u32 row = nwarp * (NT * 16) + nt * 16 + laneB_row;
                    u32 addr = sb + 2 * ASZ + swofs(row, k16 * 2 + laneB_kg);
                    LDM4(bh[nt], addr);
                    LDM4(bl[nt], addr + BSZ);
                }
                #pragma unroll
                for (int mt = 0; mt < 2; mt++)
                    #pragma unroll
                    for (int n8 = 0; n8 < 2 * NT; n8++) {
                        const u32* ph = &bh[n8 >> 1][(n8 & 1) * 2];
                        const u32* pl = &bl[n8 >> 1][(n8 & 1) * 2];
                        MMA(acc[mt][n8], ah[mt], ph[0], ph[1]);
                        MMA(acc[mt][n8], ah[mt], pl[0], pl[1]);
                        MMA(acc[mt][n8], al[mt], ph[0], ph[1]);
                    }
            }
        }
    }

    // ---- epilogue (c-frag: rows lane>>2 and +8, cols (lane&3)*2 + {0,1})
    const int r0 = lane >> 2;
    const int c0 = (lane & 3) * 2;
    #pragma unroll
    for (int mt = 0; mt < 2; mt++) {
        const int mA = bm0 + mwarp * 32 + mt * 16 + r0;
        const int mB = mA + 8;
        int pA = 0, pB = 0;
        if (EPI == 0) { pA = pidx(mA) * C; pB = pidx(mB) * C; }
        #pragma unroll
        for (int n8 = 0; n8 < 2 * NT; n8++) {
            const int gn = bn0 + nwarp * (NT * 16) + n8 * 8 + c0;
            const float* d = acc[mt][n8];
            if (EPI == 0) {
                const float b0 = bias[gn], b1 = bias[gn + 1];
                float v0 = fmaxf(d[0] + b0, 0.f), v1 = fmaxf(d[1] + b1, 0.f);
                float v2 = fmaxf(d[2] + b0, 0.f), v3 = fmaxf(d[3] + b1, 0.f);
                __nv_bfloat16 h0 = __float2bfloat16(v0), h1 = __float2bfloat16(v1);
                __nv_bfloat16 h2 = __float2bfloat16(v2), h3 = __float2bfloat16(v3);
                __nv_bfloat162 hp0; hp0.x = h0; hp0.y = h1;
                __nv_bfloat162 hp1; hp1.x = h2; hp1.y = h3;
                *(__nv_bfloat162*)&DstH[pA + gn] = hp0;
                *(__nv_bfloat162*)&DstH[pB + gn] = hp1;
                __nv_bfloat162 lp0, lp1;
                lp0.x = __float2bfloat16(v0 - __bfloat162float(h0));
                lp0.y = __float2bfloat16(v1 - __bfloat162float(h1));
                lp1.x = __float2bfloat16(v2 - __bfloat162float(h2));
                lp1.y = __float2bfloat16(v3 - __bfloat162float(h3));
                *(__nv_bfloat162*)&DstL[pA + gn] = lp0;
                *(__nv_bfloat162*)&DstL[pB + gn] = lp1;
            } else if (EPI == 1) {
                if (gn < 81) {
                    DstF[mA * 81 + gn] = d[0] + bias[gn];
                    DstF[mB * 81 + gn] = d[2] + bias[gn];
                }
                if (gn + 1 < 81) {
                    DstF[mA * 81 + gn + 1] = d[1] + bias[gn + 1];
                    DstF[mB * 81 + gn + 1] = d[3] + bias[gn + 1];
                }
            } else {
                const float b0 = bias[gn], b1 = bias[gn + 1];
                DstF[gn * NSP + mA]       = d[0] + b0;
                DstF[(gn + 1) * NSP + mA] = d[1] + b1;
                DstF[gn * NSP + mB]       = d[2] + b0;
                DstF[(gn + 1) * NSP + mB] = d[3] + b1;
            }
        }
    }
}

// ---------------- launch ----------------
extern "C" void kernel_launch(void* const* d_in, const int* in_sizes, int n_in,
                              void* d_out, int out_size)
{
    const float* x   = (const float*)d_in[0];
    const float* l1w = (const float*)d_in[1];
    const float* l1b = (const float*)d_in[2];
    const float* l2w = (const float*)d_in[3];
    const float* l2b = (const float*)d_in[4];
    const float* l3w = (const float*)d_in[5];
    const float* l3b = (const float*)d_in[6];
    const float* dw  = (const float*)d_in[7];
    const float* db  = (const float*)d_in[8];
    const float* cw  = (const float*)d_in[9];
    const float* cb  = (const float*)d_in[10];
    float* out = (float*)d_out;

    float *offs;
    __nv_bfloat16 *xph, *xpl, *fhA, *flA, *fhB, *flB, *colh, *coll;
    __nv_bfloat16 *w1h, *w1l, *w2h, *w2l, *w3h, *w3l, *wch, *wcl, *wdh, *wdl;
    cudaGetSymbolAddress((void**)&offs, g_offs);
    cudaGetSymbolAddress((void**)&xph, g_xph);  cudaGetSymbolAddress((void**)&xpl, g_xpl);
    cudaGetSymbolAddress((void**)&fhA, g_fhA);  cudaGetSymbolAddress((void**)&flA, g_flA);
    cudaGetSymbolAddress((void**)&fhB, g_fhB);  cudaGetSymbolAddress((void**)&flB, g_flB);
    cudaGetSymbolAddress((void**)&colh, g_colh); cudaGetSymbolAddress((void**)&coll, g_coll);
    cudaGetSymbolAddress((void**)&w1h, g_w1h);  cudaGetSymbolAddress((void**)&w1l, g_w1l);
    cudaGetSymbolAddress((void**)&w2h, g_w2h);  cudaGetSymbolAddress((void**)&w2l, g_w2l);
    cudaGetSymbolAddress((void**)&w3h, g_w3h);  cudaGetSymbolAddress((void**)&w3l, g_w3l);
    cudaGetSymbolAddress((void**)&wch, g_wch);  cudaGetSymbolAddress((void**)&wcl, g_wcl);
    cudaGetSymbolAddress((void**)&wdh, g_wdh);  cudaGetSymbolAddress((void**)&wdl, g_wdl);

    const int DS128 = 3 * 2 * (2 * 4096 + 2 * 128 * 64);   // 147456
    const int DS64  = 3 * 2 * (2 * 4096 + 2 * 64 * 64);    // 98304
    cudaFuncSetAttribute(tgemm<128, 0, 0>, cudaFuncAttributeMaxDynamicSharedMemorySize, DS128);
    cudaFuncSetAttribute(tgemm<64,  0, 1>, cudaFuncAttributeMaxDynamicSharedMemorySize, DS64);
    cudaFuncSetAttribute(tgemm<128, 1, 2>, cudaFuncAttributeMaxDynamicSharedMemorySize, DS128);

    zero_border<<<512, 256>>>();
    transpose_x_kernel<<<NSP, 256>>>(x);
    wtrans_all<<<1152, 256>>>(l1w, l2w, l3w, cw, dw);

    dim3 gBig(NSP / BM, 2);    // 72 x 2 = 144 CTAs (BNT=128)
    dim3 gOff(NSP / BM, 2);    // 72 x 2 = 144 CTAs (BNT=64)
    // conv1: xpad -> fA
    tgemm<128, 0, 0><<<gBig, 256, DS128>>>(xph, xpl, w1h, w1l, l1b, nullptr, fhA, flA);
    // conv2: fA -> fB
    tgemm<128, 0, 0><<<gBig, 256, DS128>>>(fhA, flA, w2h, w2l, l2b, nullptr, fhB, flB);
    // conv3: fB -> fA
    tgemm<128, 0, 0><<<gBig, 256, DS128>>>(fhB, flB, w3h, w3l, l3b, nullptr, fhA, flA);
    // offsets conv: fA -> offs (BNT=64, both column halves)
    tgemm<64, 0, 1><<<gOff, 256, DS64>>>(fhA, flA, wdh, wdl, db, offs, nullptr, nullptr);
    // deformable im2col (all 27 taps per block, L1 reuse)
    col_build_kernel<<<NSP, 256>>>();
    // deformable conv: col -> out (NCDHW)
    tgemm<128, 1, 2><<<gBig, 256, DS128>>>(colh, coll, wch, wcl, cb, out, nullptr, nullptr);
}